// round 12
// baseline (speedup 1.0000x reference)
#include <cuda_runtime.h>
#include <math.h>
#include <stdint.h>

// Problem constants (fixed shapes for this problem instance)
#define S_LEN  1024
#define DM     4096
#define NH     32
#define HD     128
#define CACHE  2048
#define TTOT   (CACHE + S_LEN)   // 3072 total kv positions

// Scratch (device globals: allocation-free rule)
__device__ float g_xn[S_LEN * DM];
__device__ float g_q [S_LEN * DM];
__device__ float g_k [S_LEN * DM];
__device__ float g_v [S_LEN * DM];
__device__ float g_at[S_LEN * DM];
__device__ float g_kc[(size_t)TTOT * DM];          // tf32-rounded K [T,H,HD]
__device__ float g_vt[(size_t)NH * HD * TTOT];     // tf32-rounded V^T [H,HD,T]

// ---------------------------------------------------------------------------
// Common tensor-core helpers
// ---------------------------------------------------------------------------
__device__ __forceinline__ uint32_t f2tf32(float x) {
    uint32_t r;
    asm("cvt.rna.tf32.f32 %0, %1;" : "=r"(r) : "f"(x));
    return r;
}
__device__ __forceinline__ uint32_t u2tf32(uint32_t x) {
    uint32_t r;
    asm("cvt.rna.tf32.f32 %0, %1;" : "=r"(r) : "r"(x));
    return r;
}

__device__ __forceinline__ void mma_tf32(float c[4], const uint32_t a[4], const uint32_t b[2]) {
    asm volatile(
        "mma.sync.aligned.m16n8k8.row.col.f32.tf32.tf32.f32 "
        "{%0,%1,%2,%3}, {%4,%5,%6,%7}, {%8,%9}, {%0,%1,%2,%3};"
        : "+f"(c[0]), "+f"(c[1]), "+f"(c[2]), "+f"(c[3])
        : "r"(a[0]), "r"(a[1]), "r"(a[2]), "r"(a[3]), "r"(b[0]), "r"(b[1]));
}

__device__ __forceinline__ void ldsm4(uint32_t r[4], uint32_t addr) {
    asm volatile("ldmatrix.sync.aligned.m8n8.x4.shared.b16 {%0,%1,%2,%3}, [%4];"
        : "=r"(r[0]), "=r"(r[1]), "=r"(r[2]), "=r"(r[3]) : "r"(addr));
}

__device__ __forceinline__ void cp16(uint32_t dst, const void* src) {
    asm volatile("cp.async.cg.shared.global [%0], [%1], 16;" :: "r"(dst), "l"(src));
}
#define CP_COMMIT()  asm volatile("cp.async.commit_group;")
#define CP_WAIT0()   asm volatile("cp.async.wait_group 0;")
#define CP_WAIT1()   asm volatile("cp.async.wait_group 1;")

// ---------------------------------------------------------------------------
// RMSNorm: one block per row (4096 elems), 256 threads. Emits rna tf32.
// ---------------------------------------------------------------------------
__global__ void rmsnorm_kernel(const float* __restrict__ xs,
                               const float* __restrict__ w)
{
    const int row = blockIdx.x;
    const int tid = threadIdx.x;
    const float* x = xs + (size_t)row * DM;
    float* y = g_xn + (size_t)row * DM;

    float ss = 0.f;
#pragma unroll
    for (int i = 0; i < 4; i++) {
        float4 v = *(const float4*)(x + (i * 256 + tid) * 4);
        ss += v.x * v.x + v.y * v.y + v.z * v.z + v.w * v.w;
    }
#pragma unroll
    for (int off = 16; off; off >>= 1)
        ss += __shfl_xor_sync(0xffffffffu, ss, off);

    __shared__ float red[8];
    __shared__ float s_inv;
    if ((tid & 31) == 0) red[tid >> 5] = ss;
    __syncthreads();
    if (tid == 0) {
        float t = 0.f;
#pragma unroll
        for (int i = 0; i < 8; i++) t += red[i];
        s_inv = rsqrtf(t / (float)DM + 1e-6f);
    }
    __syncthreads();
    const float inv = s_inv;
#pragma unroll
    for (int i = 0; i < 4; i++) {
        int base = (i * 256 + tid) * 4;
        float4 v = *(const float4*)(x + base);
        float4 g = *(const float4*)(w + base);
        uint4 u;
        u.x = f2tf32(v.x * inv * g.x);
        u.y = f2tf32(v.y * inv * g.y);
        u.z = f2tf32(v.z * inv * g.z);
        u.w = f2tf32(v.w * inv * g.w);
        *(uint4*)(y + base) = u;
    }
}

// ---------------------------------------------------------------------------
// TF32 tensor-core GEMM (NT): tile 128x128x32, 3-stage cp.async, ldmatrix
// fragments, stride 36. B raw fp32, rounded in registers. A pre-rounded.
// FUSED: grid.x covers q|k|v thirds; V third RNA-rounded on store -> g_v.
// ---------------------------------------------------------------------------
#define GSTR 36
#define ATW  (128 * GSTR)
#define STW  (2 * ATW)
#define NST  3
#define GEMM_SMEM_BYTES (NST * STW * 4)   // 110592 B

template <bool FUSED>
__global__ void __launch_bounds__(256, 2)
sgemm_tc(const float* __restrict__ A,
         const float* __restrict__ B0, const float* __restrict__ B1,
         const float* __restrict__ B2,
         float* __restrict__ C0, int N, int K)
{
    extern __shared__ uint32_t gsm[];
    const uint32_t sbase = (uint32_t)__cvta_generic_to_shared(gsm);

    const int tid  = threadIdx.x;
    const int lane = tid & 31;
    const int warp = tid >> 5;
    const int g    = lane >> 2;
    const int tig  = lane & 3;
    const int m_base = (warp >> 2) * 64;
    const int n_base = (warp & 3) * 32;

    const float* B = B0;
    float* C = C0;
    int bxx = blockIdx.x;
    bool round_out = false;
    if (FUSED) {
        const int third = blockIdx.x >> 5;       // 0:q 1:k 2:v
        bxx = blockIdx.x & 31;
        if (third == 1)      { B = B1; C = g_k; }
        else if (third == 2) { B = B2; C = g_v; round_out = true; }
    }

    const int r0 = tid >> 3;
    const int c0 = (tid & 7) << 2;
    const float* Ag = A + (size_t)(blockIdx.y * 128 + r0) * K + c0;
    const float* Bg = B + (size_t)(bxx * 128 + r0) * K + c0;
    const uint32_t d0 = (uint32_t)(r0 * GSTR + c0) * 4;
    const size_t gstep = (size_t)32 * K;
    const uint32_t sstep = (uint32_t)(32 * GSTR) * 4;

    auto issue = [&](int kt) {
        const uint32_t st = sbase + (uint32_t)(kt % NST) * (STW * 4);
        const int ko = kt << 5;
        const float* a = Ag + ko;
        const float* b = Bg + ko;
#pragma unroll
        for (int it = 0; it < 4; it++) {
            cp16(st + d0 + it * sstep, a + it * gstep);
            cp16(st + ATW * 4 + d0 + it * sstep, b + it * gstep);
        }
        CP_COMMIT();
    };

    float c[4][4][4];
#pragma unroll
    for (int mt = 0; mt < 4; mt++)
#pragma unroll
        for (int nt = 0; nt < 4; nt++)
#pragma unroll
            for (int i = 0; i < 4; i++) c[mt][nt][i] = 0.f;

    issue(0); issue(1);

    const int arow  = m_base + (lane & 15);
    const int acolh = (lane >> 2) & 4;
    const int brow  = n_base + (lane & 7) + ((lane >> 1) & 8);
    const int bcolh = (lane >> 1) & 4;

    const int KT = K >> 5;
    for (int kt = 0; kt < KT; kt++) {
        if (kt + 1 < KT) { CP_WAIT1(); } else { CP_WAIT0(); }
        __syncthreads();
        if (kt + 2 < KT) issue(kt + 2);

        const uint32_t tA = sbase + (uint32_t)(kt % NST) * (STW * 4);
        const uint32_t tB = tA + ATW * 4;
#pragma unroll
        for (int kk = 0; kk < 4; kk++) {
            uint32_t a[4][4], b[2][4];
#pragma unroll
            for (int mt = 0; mt < 4; mt++)
                ldsm4(a[mt], tA + (uint32_t)((arow + mt * 16) * GSTR + kk * 8 + acolh) * 4);
            ldsm4(b[0], tB + (uint32_t)(brow * GSTR + kk * 8 + bcolh) * 4);
            ldsm4(b[1], tB + (uint32_t)((brow + 16) * GSTR + kk * 8 + bcolh) * 4);
#pragma unroll
            for (int i = 0; i < 4; i++) {
                b[0][i] = u2tf32(b[0][i]);
                b[1][i] = u2tf32(b[1][i]);
            }
#pragma unroll
            for (int mt = 0; mt < 4; mt++)
#pragma unroll
                for (int nt = 0; nt < 4; nt++) {
                    uint32_t bb[2] = { b[nt >> 1][(nt & 1) * 2],
                                       b[nt >> 1][(nt & 1) * 2 + 1] };
                    mma_tf32(c[mt][nt], a[mt], bb);
                }
        }
    }

    const int crow = blockIdx.y * 128 + m_base + g;
    const int ccol = bxx * 128 + n_base + 2 * tig;
#pragma unroll
    for (int mt = 0; mt < 4; mt++) {
#pragma unroll
        for (int nt = 0; nt < 4; nt++) {
            const int row = crow + mt * 16;
            const int col = ccol + nt * 8;
            if (FUSED && round_out) {
                uint32_t* p0 = (uint32_t*)(C + (size_t)row * N + col);
                uint32_t* p1 = (uint32_t*)(C + (size_t)(row + 8) * N + col);
                p0[0] = f2tf32(c[mt][nt][0]);
                p0[1] = f2tf32(c[mt][nt][1]);
                p1[0] = f2tf32(c[mt][nt][2]);
                p1[1] = f2tf32(c[mt][nt][3]);
            } else {
                *(float2*)(C + (size_t)row * N + col) =
                    make_float2(c[mt][nt][0], c[mt][nt][1]);
                *(float2*)(C + (size_t)(row + 8) * N + col) =
                    make_float2(c[mt][nt][2], c[mt][nt][3]);
            }
        }
    }
}

// ---------------------------------------------------------------------------
// Merged RoPE: q in-place (raw fp32); k -> g_kc[CACHE:] RNA-rounded.
// ---------------------------------------------------------------------------
__global__ void rope_qk_kernel()
{
    int idx = blockIdx.x * blockDim.x + threadIdx.x;
    int i = idx & 63;
    int h = (idx >> 6) & (NH - 1);
    int s = idx >> 11;

    float pos = (float)(s + CACHE);
    float inv_freq = exp2f(-(float)i * (13.287712379549449f / 64.f));
    float ang = pos * inv_freq;
    float sn, cs;
    sincosf(ang, &sn, &cs);

    const size_t off = ((size_t)(s * NH + h) * HD) + i;
    // q: in-place
    {
        float* p = g_q + off;
        float x1 = p[0];
        float x2 = p[64];
        p[0]  = x1 * cs - x2 * sn;
        p[64] = x2 * cs + x1 * sn;
    }
    // k: rounded into g_kc[CACHE + s]
    {
        const float* p = g_k + off;
        float x1 = p[0];
        float x2 = p[64];
        uint32_t* d = (uint32_t*)(g_kc + (size_t)(CACHE + s) * DM + h * HD + i);
        d[0]  = f2tf32(x1 * cs - x2 * sn);
        d[64] = f2tf32(x2 * cs + x1 * sn);
    }
}

// ---------------------------------------------------------------------------
// Convert the K cache part (t < CACHE) into RNA-rounded g_kc.
// ---------------------------------------------------------------------------
__global__ void convert_k_cache_kernel(const float* __restrict__ cache_k)
{
    const size_t elem = ((size_t)blockIdx.x * blockDim.x + threadIdx.x) * 4;
    float4 k = *(const float4*)(cache_k + elem);
    uint4 ko;
    ko.x = f2tf32(k.x); ko.y = f2tf32(k.y); ko.z = f2tf32(k.z); ko.w = f2tf32(k.w);
    *(uint4*)(g_kc + elem) = ko;
}

// ---------------------------------------------------------------------------
// Build V^T [H, HD, T] (tf32-rounded) from cache_v (raw, rounded here) and
// g_v (V-GEMM output, already rounded). Tiled smem transpose, coalesced
// both directions. Grid: (NH, TTOT/64), 256 threads.
// ---------------------------------------------------------------------------
#define TPAD 133
__global__ void transpose_v_kernel(const float* __restrict__ cache_v)
{
    __shared__ float ts[64 * TPAD];
    const int h  = blockIdx.x;
    const int t0 = blockIdx.y * 64;
    const int tid = threadIdx.x;

    // Load 64 t-rows x 128 hd (coalesced), rounding the cache part.
#pragma unroll
    for (int it = 0; it < 8; it++) {
        int i = it * 256 + tid;        // 2048 float4 chunks
        int r = i >> 5;                // t row 0..63
        int c = (i & 31) << 2;         // hd 0..124
        int t = t0 + r;
        float4 v;
        if (t < CACHE) {
            v = *(const float4*)(cache_v + ((size_t)t * NH + h) * HD + c);
            uint4 u;
            u.x = f2tf32(v.x); u.y = f2tf32(v.y);
            u.z = f2tf32(v.z); u.w = f2tf32(v.w);
            v = *(float4*)&u;
        } else {
            v = *(const float4*)(g_v + (size_t)(t - CACHE) * DM + h * HD + c);
        }
        ts[r * TPAD + c + 0] = v.x;
        ts[r * TPAD + c + 1] = v.y;
        ts[r * TPAD + c + 2] = v.z;
        ts[r * TPAD + c + 3] = v.w;
    }
    __syncthreads();

    // Write 128 hd-rows x 64 t (coalesced along T).
#pragma unroll
    for (int it = 0; it < 8; it++) {
        int i = it * 256 + tid;        // 2048 float4 chunks
        int hd = i >> 4;               // 0..127
        int c  = (i & 15) << 2;        // t offset 0..60
        float4 o;
        o.x = ts[(c + 0) * TPAD + hd];
        o.y = ts[(c + 1) * TPAD + hd];
        o.z = ts[(c + 2) * TPAD + hd];
        o.w = ts[(c + 3) * TPAD + hd];
        *(float4*)(g_vt + ((size_t)(h * HD + hd)) * TTOT + t0 + c) = o;
    }
}

// ---------------------------------------------------------------------------
// Tensor-core flash attention. K via ldmatrix (proven), V now ALSO via
// ldmatrix from transposed V tiles (rows=hd, cols=key, stride 68).
// 512 one-job blocks, long jobs first (proven schedule).
// ---------------------------------------------------------------------------
#define KQSTR 132
#define VSTR2 68
#define PSTR  68

#define QS_WORDS (64 * KQSTR)
#define KS_WORDS (64 * KQSTR)
#define VS_WORDS (128 * VSTR2)
#define PS_WORDS (64 * PSTR)

#define FLASH_SMEM_WORDS (QS_WORDS + 2*KS_WORDS + 2*VS_WORDS + PS_WORDS + 192)
#define FLASH_SMEM_BYTES (FLASH_SMEM_WORDS * 4)

__global__ void __launch_bounds__(256, 1)
flash_tc_kernel()
{
    extern __shared__ uint32_t fsm[];
    uint32_t* Qs  = fsm;
    uint32_t* Ks0 = Qs  + QS_WORDS;
    uint32_t* Ks1 = Ks0 + KS_WORDS;
    uint32_t* Vs0 = Ks1 + KS_WORDS;
    uint32_t* Vs1 = Vs0 + VS_WORDS;
    uint32_t* Ps  = Vs1 + VS_WORDS;
    float* m_s    = (float*)(Ps + PS_WORDS);
    float* l_s    = m_s + 64;
    float* salpha = l_s + 64;
    float* PsF    = (float*)Ps;

    const int h  = blockIdx.x;
    const int qt = (S_LEN / 64 - 1) - blockIdx.y;
    const int tid = threadIdx.x;
    const int lane = tid & 31;
    const int warp = tid >> 5;
    const int g    = lane >> 2;
    const int tig  = lane & 3;
    const int wr   = warp >> 1;
    const int wc   = warp & 1;
    const int m0   = wr * 16;

    const uint32_t qs_a  = (uint32_t)__cvta_generic_to_shared(Qs);
    const uint32_t ks0_a = (uint32_t)__cvta_generic_to_shared(Ks0);
    const uint32_t ks1_a = (uint32_t)__cvta_generic_to_shared(Ks1);
    const uint32_t vs0_a = (uint32_t)__cvta_generic_to_shared(Vs0);
    const uint32_t vs1_a = (uint32_t)__cvta_generic_to_shared(Vs1);
    const uint32_t ps_a  = (uint32_t)__cvta_generic_to_shared(Ps);

    const float qscale = 0.08838834764831845f;
#pragma unroll
    for (int it = 0; it < 8; it++) {
        int idx = it * 256 + tid;
        int r = idx >> 5;
        int c = (idx & 31) << 2;
        float4 v = *(const float4*)(g_q + (size_t)(qt * 64 + r) * DM + h * HD + c);
        uint4 u;
        u.x = f2tf32(v.x * qscale);
        u.y = f2tf32(v.y * qscale);
        u.z = f2tf32(v.z * qscale);
        u.w = f2tf32(v.w * qscale);
        *(uint4*)&Qs[r * KQSTR + c] = u;
    }
    if (tid < 64) { m_s[tid] = -1e30f; l_s[tid] = 0.f; }

    auto issue_kv = [&](int kt, int b) {
        const int t0 = kt * 64;
        const uint32_t ka = b ? ks1_a : ks0_a;
        const uint32_t va = b ? vs1_a : vs0_a;
        const float* vbase = g_vt + (size_t)h * HD * TTOT + t0;
#pragma unroll
        for (int it = 0; it < 8; it++) {
            int idx = it * 256 + tid;
            // K chunk: [64 t rows][128 hd], row-major by t
            int r = idx >> 5;
            int c = (idx & 31) << 2;
            cp16(ka + (r * KQSTR + c) * 4,
                 g_kc + (size_t)(t0 + r) * DM + h * HD + c);
            // V chunk: transposed tile [128 hd rows][64 t]
            int hr = idx >> 4;
            int tc = (idx & 15) << 2;
            cp16(va + (hr * VSTR2 + tc) * 4,
                 vbase + (size_t)hr * TTOT + tc);
        }
        CP_COMMIT();
    };

    issue_kv(0, 0);

    float oacc[8][4];
#pragma unroll
    for (int nt = 0; nt < 8; nt++)
#pragma unroll
        for (int i = 0; i < 4; i++) oacc[nt][i] = 0.f;

    const int arow  = m0 + (lane & 15);
    const int acolh = (lane >> 2) & 4;
    const int brow  = wc * 32 + (lane & 7) + ((lane >> 1) & 8);
    const int vrow  = wc * 64 + (lane & 7) + ((lane >> 1) & 8);
    const int bcolh = (lane >> 1) & 4;

    const int ntiles = 33 + qt;
    int p = 0;
    for (int kt = 0; kt < ntiles; kt++) {
        CP_WAIT0();
        __syncthreads();
        if (kt + 1 < ntiles) issue_kv(kt + 1, p ^ 1);

        const uint32_t ka = p ? ks1_a : ks0_a;
        const uint32_t va = p ? vs1_a : vs0_a;

        // ---- S = Q K^T (warp tile 16x32), ldmatrix fragments ----
        float sacc[4][4];
#pragma unroll
        for (int nt = 0; nt < 4; nt++)
#pragma unroll
            for (int i = 0; i < 4; i++) sacc[nt][i] = 0.f;

#pragma unroll
        for (int ks = 0; ks < 16; ks++) {
            const int k0 = ks * 8;
            uint32_t a[4], b[2][4];
            ldsm4(a, qs_a + (uint32_t)(arow * KQSTR + k0 + acolh) * 4);
            ldsm4(b[0], ka + (uint32_t)(brow * KQSTR + k0 + bcolh) * 4);
            ldsm4(b[1], ka + (uint32_t)((brow + 16) * KQSTR + k0 + bcolh) * 4);
#pragma unroll
            for (int nt = 0; nt < 4; nt++) {
                uint32_t bb[2] = { b[nt >> 1][(nt & 1) * 2],
                                   b[nt >> 1][(nt & 1) * 2 + 1] };
                mma_tf32(sacc[nt], a, bb);
            }
        }

        const bool diag = (kt == ntiles - 1);
        const int r0 = m0 + g, r1 = m0 + g + 8;
#pragma unroll
        for (int nt = 0; nt < 4; nt++) {
            int col = wc * 32 + nt * 8 + 2 * tig;
            float v0 = sacc[nt][0], v1 = sacc[nt][1];
            float v2 = sacc[nt][2], v3 = sacc[nt][3];
            if (diag) {
                if (col     > r0) v0 = -1e30f;
                if (col + 1 > r0) v1 = -1e30f;
                if (col     > r1) v2 = -1e30f;
                if (col + 1 > r1) v3 = -1e30f;
            }
            *(float2*)&PsF[r0 * PSTR + col] = make_float2(v0, v1);
            *(float2*)&PsF[r1 * PSTR + col] = make_float2(v2, v3);
        }
        __syncthreads();

        // ---- online softmax: 4 threads per row ----
        {
            const int row = tid >> 2;
            const int qd  = tid & 3;
            float* pr = PsF + row * PSTR + qd * 16;
            float4 x0 = *(float4*)(pr + 0);
            float4 x1 = *(float4*)(pr + 4);
            float4 x2 = *(float4*)(pr + 8);
            float4 x3 = *(float4*)(pr + 12);
            float mp = fmaxf(fmaxf(fmaxf(x0.x, x0.y), fmaxf(x0.z, x0.w)),
                             fmaxf(fmaxf(x1.x, x1.y), fmaxf(x1.z, x1.w)));
            mp = fmaxf(mp, fmaxf(fmaxf(fmaxf(x2.x, x2.y), fmaxf(x2.z, x2.w)),
                                 fmaxf(fmaxf(x3.x, x3.y), fmaxf(x3.z, x3.w))));
            mp = fmaxf(mp, __shfl_xor_sync(0xffffffffu, mp, 1));
            mp = fmaxf(mp, __shfl_xor_sync(0xffffffffu, mp, 2));
            const float mold = m_s[row];
            const float mx = fmaxf(mold, mp);
            float sum;
            {
                uint4 u;
                float s = 0.f;
                float p0, p1, p2, p3;
                p0 = __expf(x0.x - mx); p1 = __expf(x0.y - mx);
                p2 = __expf(x0.z - mx); p3 = __expf(x0.w - mx);
                s += (p0 + p1) + (p2 + p3);
                u.x = f2tf32(p0); u.y = f2tf32(p1); u.z = f2tf32(p2); u.w = f2tf32(p3);
                *(uint4*)(pr + 0) = u;
                p0 = __expf(x1.x - mx); p1 = __expf(x1.y - mx);
                p2 = __expf(x1.z - mx); p3 = __expf(x1.w - mx);
                s += (p0 + p1) + (p2 + p3);
                u.x = f2tf32(p0); u.y = f2tf32(p1); u.z = f2tf32(p2); u.w = f2tf32(p3);
                *(uint4*)(pr + 4) = u;
                p0 = __expf(x2.x - mx); p1 = __expf(x2.y - mx);
                p2 = __expf(x2.z - mx); p3 = __expf(x2.w - mx);
                s += (p0 + p1) + (p2 + p3);
                u.x = f2tf32(p0); u.y = f2tf32(p1); u.z = f2tf32(p2); u.w = f2tf32(p3);
                *(uint4*)(pr + 8) = u;
                p0 = __expf(x3.x - mx); p1 = __expf(x3.y - mx);
                p2 = __expf(x3.z - mx); p3 = __expf(x3.w - mx);
                s += (p0 + p1) + (p2 + p3);
                u.x = f2tf32(p0); u.y = f2tf32(p1); u.z = f2tf32(p2); u.w = f2tf32(p3);
                *(uint4*)(pr + 12) = u;
                sum = s;
            }
            sum += __shfl_xor_sync(0xffffffffu, sum, 1);
            sum += __shfl_xor_sync(0xffffffffu, sum, 2);
            __syncwarp();
            if (qd == 0) {
                float alpha = __expf(mold - mx);
                l_s[row] = l_s[row] * alpha + sum;
                m_s[row] = mx;
                salpha[row] = alpha;
            }
        }
        __syncthreads();

        // ---- rescale O, then O += P V (warp tile 16x64, V via ldmatrix) ----
        {
            const float alo = salpha[m0 + g];
            const float ahi = salpha[m0 + g + 8];
#pragma unroll
            for (int nt = 0; nt < 8; nt++) {
                oacc[nt][0] *= alo; oacc[nt][1] *= alo;
                oacc[nt][2] *= ahi; oacc[nt][3] *= ahi;
            }
#pragma unroll
            for (int ks = 0; ks < 8; ks++) {
                const int k0 = ks * 8;
                uint32_t a[4];
                ldsm4(a, ps_a + (uint32_t)(arow * PSTR + k0 + acolh) * 4);
                uint32_t vb[4][4];
#pragma unroll
                for (int j = 0; j < 4; j++)
                    ldsm4(vb[j], va + (uint32_t)((vrow + j * 16) * VSTR2 + k0 + bcolh) * 4);
#pragma unroll
                for (int nt = 0; nt < 8; nt++) {
                    uint32_t bb[2] = { vb[nt >> 1][(nt & 1) * 2],
                                       vb[nt >> 1][(nt & 1) * 2 + 1] };
                    mma_tf32(oacc[nt], a, bb);
                }
            }
        }
        p ^= 1;
    }

    __syncthreads();
    const float ilo = 1.f / l_s[m0 + g];
    const float ihi = 1.f / l_s[m0 + g + 8];
    const int grow = qt * 64 + m0 + g;
#pragma unroll
    for (int nt = 0; nt < 8; nt++) {
        const int col = h * HD + wc * 64 + nt * 8 + 2 * tig;
        uint32_t* d0 = (uint32_t*)(g_at + (size_t)grow * DM + col);
        uint32_t* d1 = (uint32_t*)(g_at + (size_t)(grow + 8) * DM + col);
        d0[0] = f2tf32(oacc[nt][0] * ilo);
        d0[1] = f2tf32(oacc[nt][1] * ilo);
        d1[0] = f2tf32(oacc[nt][2] * ihi);
        d1[1] = f2tf32(oacc[nt][3] * ihi);
    }
}

// ---------------------------------------------------------------------------
// Launch
// ---------------------------------------------------------------------------
extern "C" void kernel_launch(void* const* d_in, const int* in_sizes, int n_in,
                              void* d_out, int out_size)
{
    (void)in_sizes; (void)n_in; (void)out_size;
    const float* xs      = (const float*)d_in[0];
    const float* cache_k = (const float*)d_in[1];
    const float* cache_v = (const float*)d_in[2];
    const float* norm_w  = (const float*)d_in[3];
    const float* wq      = (const float*)d_in[4];
    const float* wk      = (const float*)d_in[5];
    const float* wv      = (const float*)d_in[6];
    const float* wo      = (const float*)d_in[7];
    float* out = (float*)d_out;

    float *p_xn, *p_q, *p_at;
    cudaGetSymbolAddress((void**)&p_xn, g_xn);
    cudaGetSymbolAddress((void**)&p_q,  g_q);
    cudaGetSymbolAddress((void**)&p_at, g_at);

    cudaFuncSetAttribute((const void*)&sgemm_tc<true>,
                         cudaFuncAttributeMaxDynamicSharedMemorySize,
                         GEMM_SMEM_BYTES);
    cudaFuncSetAttribute((const void*)&sgemm_tc<false>,
                         cudaFuncAttributeMaxDynamicSharedMemorySize,
                         GEMM_SMEM_BYTES);
    cudaFuncSetAttribute((const void*)&flash_tc_kernel,
                         cudaFuncAttributeMaxDynamicSharedMemorySize,
                         FLASH_SMEM_BYTES);

    // 1) RMSNorm (emits tf32-rounded xn)
    rmsnorm_kernel<<<S_LEN, 256>>>(xs, norm_w);

    // 2) K cache conversion
    {
        const size_t n4 = (size_t)CACHE * DM / 4;
        convert_k_cache_kernel<<<(unsigned)(n4 / 256), 256>>>(cache_k);
    }

    // 3) Fused QKV projection (raw weights, B rounded in-register):
    //    q -> g_q, k -> g_k, v -> g_v (rounded).
    {
        dim3 gq(3 * DM / 128, S_LEN / 128);   // (96, 8)
        sgemm_tc<true><<<gq, 256, GEMM_SMEM_BYTES>>>(
            p_xn, wq, wk, wv, p_q, DM, DM);
    }

    // 4) Merged RoPE: q in-place; k -> rounded into g_kc[CACHE:]
    rope_qk_kernel<<<(S_LEN * NH * 64) / 256, 256>>>();

    // 5) Build transposed V (cache + new) -> g_vt
    transpose_v_kernel<<<dim3(NH, TTOT / 64), 256>>>(cache_v);

    // 6) Tensor-core flash attention
    flash_tc_kernel<<<dim3(NH, S_LEN / 64), 256, FLASH_SMEM_BYTES>>>();

    // 7) Output projection -> d_out (raw wo, B rounded in-register)
    {
        dim3 gg(DM / 128, S_LEN / 128);
        sgemm_tc<false><<<gg, 256, GEMM_SMEM_BYTES>>>(
            p_at, wo, nullptr, nullptr, out, DM, DM);
    }
}

// round 13
// speedup vs baseline: 1.0216x; 1.0216x over previous
#include <cuda_runtime.h>
#include <math.h>
#include <stdint.h>

// Problem constants (fixed shapes for this problem instance)
#define S_LEN  1024
#define DM     4096
#define NH     32
#define HD     128
#define CACHE  2048
#define TTOT   (CACHE + S_LEN)   // 3072 total kv positions

// Scratch (device globals: allocation-free rule)
__device__ float g_xn[S_LEN * DM];
__device__ float g_q [S_LEN * DM];
__device__ float g_k [S_LEN * DM];
__device__ float g_at[S_LEN * DM];
__device__ float g_kc[(size_t)TTOT * DM];   // tf32-rounded unified K [T,H,HD]
__device__ float g_vc[(size_t)TTOT * DM];   // tf32-rounded unified V [T,H,HD]

// ---------------------------------------------------------------------------
// Common tensor-core helpers
// ---------------------------------------------------------------------------
__device__ __forceinline__ uint32_t f2tf32(float x) {
    uint32_t r;
    asm("cvt.rna.tf32.f32 %0, %1;" : "=r"(r) : "f"(x));
    return r;
}
__device__ __forceinline__ uint32_t u2tf32(uint32_t x) {
    uint32_t r;
    asm("cvt.rna.tf32.f32 %0, %1;" : "=r"(r) : "r"(x));
    return r;
}

__device__ __forceinline__ void mma_tf32(float c[4], const uint32_t a[4], const uint32_t b[2]) {
    asm volatile(
        "mma.sync.aligned.m16n8k8.row.col.f32.tf32.tf32.f32 "
        "{%0,%1,%2,%3}, {%4,%5,%6,%7}, {%8,%9}, {%0,%1,%2,%3};"
        : "+f"(c[0]), "+f"(c[1]), "+f"(c[2]), "+f"(c[3])
        : "r"(a[0]), "r"(a[1]), "r"(a[2]), "r"(a[3]), "r"(b[0]), "r"(b[1]));
}

__device__ __forceinline__ void ldsm4(uint32_t r[4], uint32_t addr) {
    asm volatile("ldmatrix.sync.aligned.m8n8.x4.shared.b16 {%0,%1,%2,%3}, [%4];"
        : "=r"(r[0]), "=r"(r[1]), "=r"(r[2]), "=r"(r[3]) : "r"(addr));
}

__device__ __forceinline__ void cp16(uint32_t dst, const void* src) {
    asm volatile("cp.async.cg.shared.global [%0], [%1], 16;" :: "r"(dst), "l"(src));
}
#define CP_COMMIT()  asm volatile("cp.async.commit_group;")
#define CP_WAIT0()   asm volatile("cp.async.wait_group 0;")
#define CP_WAIT1()   asm volatile("cp.async.wait_group 1;")

#define BAR_PAIR(id) asm volatile("bar.sync %0, 64;" :: "r"(id) : "memory")

// ---------------------------------------------------------------------------
// RMSNorm: one block per row (4096 elems), 256 threads. Emits rna tf32.
// ---------------------------------------------------------------------------
__global__ void rmsnorm_kernel(const float* __restrict__ xs,
                               const float* __restrict__ w)
{
    const int row = blockIdx.x;
    const int tid = threadIdx.x;
    const float* x = xs + (size_t)row * DM;
    float* y = g_xn + (size_t)row * DM;

    float ss = 0.f;
#pragma unroll
    for (int i = 0; i < 4; i++) {
        float4 v = *(const float4*)(x + (i * 256 + tid) * 4);
        ss += v.x * v.x + v.y * v.y + v.z * v.z + v.w * v.w;
    }
#pragma unroll
    for (int off = 16; off; off >>= 1)
        ss += __shfl_xor_sync(0xffffffffu, ss, off);

    __shared__ float red[8];
    __shared__ float s_inv;
    if ((tid & 31) == 0) red[tid >> 5] = ss;
    __syncthreads();
    if (tid == 0) {
        float t = 0.f;
#pragma unroll
        for (int i = 0; i < 8; i++) t += red[i];
        s_inv = rsqrtf(t / (float)DM + 1e-6f);
    }
    __syncthreads();
    const float inv = s_inv;
#pragma unroll
    for (int i = 0; i < 4; i++) {
        int base = (i * 256 + tid) * 4;
        float4 v = *(const float4*)(x + base);
        float4 g = *(const float4*)(w + base);
        uint4 u;
        u.x = f2tf32(v.x * inv * g.x);
        u.y = f2tf32(v.y * inv * g.y);
        u.z = f2tf32(v.z * inv * g.z);
        u.w = f2tf32(v.w * inv * g.w);
        *(uint4*)(y + base) = u;
    }
}

// ---------------------------------------------------------------------------
// TF32 tensor-core GEMM (NT): tile 128x128x32, 3-stage cp.async, ldmatrix
// fragments, stride 36. B raw fp32, rounded in registers. A pre-rounded.
// FUSED: grid.x covers q|k|v thirds; V third RNA-rounded on store -> CV.
// ---------------------------------------------------------------------------
#define GSTR 36
#define ATW  (128 * GSTR)
#define STW  (2 * ATW)
#define NST  3
#define GEMM_SMEM_BYTES (NST * STW * 4)   // 110592 B

template <bool FUSED>
__global__ void __launch_bounds__(256, 2)
sgemm_tc(const float* __restrict__ A,
         const float* __restrict__ B0, const float* __restrict__ B1,
         const float* __restrict__ B2,
         float* __restrict__ C0, float* __restrict__ CV, int N, int K)
{
    extern __shared__ uint32_t gsm[];
    const uint32_t sbase = (uint32_t)__cvta_generic_to_shared(gsm);

    const int tid  = threadIdx.x;
    const int lane = tid & 31;
    const int warp = tid >> 5;
    const int g    = lane >> 2;
    const int tig  = lane & 3;
    const int m_base = (warp >> 2) * 64;
    const int n_base = (warp & 3) * 32;

    const float* B = B0;
    float* C = C0;
    int bxx = blockIdx.x;
    bool round_out = false;
    if (FUSED) {
        const int third = blockIdx.x >> 5;       // 0:q 1:k 2:v
        bxx = blockIdx.x & 31;
        if (third == 1)      { B = B1; C = g_k; }
        else if (third == 2) { B = B2; C = CV; round_out = true; }
    }

    const int r0 = tid >> 3;
    const int c0 = (tid & 7) << 2;
    const float* Ag = A + (size_t)(blockIdx.y * 128 + r0) * K + c0;
    const float* Bg = B + (size_t)(bxx * 128 + r0) * K + c0;
    const uint32_t d0 = (uint32_t)(r0 * GSTR + c0) * 4;
    const size_t gstep = (size_t)32 * K;
    const uint32_t sstep = (uint32_t)(32 * GSTR) * 4;

    auto issue = [&](int kt) {
        const uint32_t st = sbase + (uint32_t)(kt % NST) * (STW * 4);
        const int ko = kt << 5;
        const float* a = Ag + ko;
        const float* b = Bg + ko;
#pragma unroll
        for (int it = 0; it < 4; it++) {
            cp16(st + d0 + it * sstep, a + it * gstep);
            cp16(st + ATW * 4 + d0 + it * sstep, b + it * gstep);
        }
        CP_COMMIT();
    };

    float c[4][4][4];
#pragma unroll
    for (int mt = 0; mt < 4; mt++)
#pragma unroll
        for (int nt = 0; nt < 4; nt++)
#pragma unroll
            for (int i = 0; i < 4; i++) c[mt][nt][i] = 0.f;

    issue(0); issue(1);

    const int arow  = m_base + (lane & 15);
    const int acolh = (lane >> 2) & 4;
    const int brow  = n_base + (lane & 7) + ((lane >> 1) & 8);
    const int bcolh = (lane >> 1) & 4;

    const int KT = K >> 5;
    for (int kt = 0; kt < KT; kt++) {
        if (kt + 1 < KT) { CP_WAIT1(); } else { CP_WAIT0(); }
        __syncthreads();
        if (kt + 2 < KT) issue(kt + 2);

        const uint32_t tA = sbase + (uint32_t)(kt % NST) * (STW * 4);
        const uint32_t tB = tA + ATW * 4;
#pragma unroll
        for (int kk = 0; kk < 4; kk++) {
            uint32_t a[4][4], b[2][4];
#pragma unroll
            for (int mt = 0; mt < 4; mt++)
                ldsm4(a[mt], tA + (uint32_t)((arow + mt * 16) * GSTR + kk * 8 + acolh) * 4);
            ldsm4(b[0], tB + (uint32_t)(brow * GSTR + kk * 8 + bcolh) * 4);
            ldsm4(b[1], tB + (uint32_t)((brow + 16) * GSTR + kk * 8 + bcolh) * 4);
#pragma unroll
            for (int i = 0; i < 4; i++) {
                b[0][i] = u2tf32(b[0][i]);
                b[1][i] = u2tf32(b[1][i]);
            }
#pragma unroll
            for (int mt = 0; mt < 4; mt++)
#pragma unroll
                for (int nt = 0; nt < 4; nt++) {
                    uint32_t bb[2] = { b[nt >> 1][(nt & 1) * 2],
                                       b[nt >> 1][(nt & 1) * 2 + 1] };
                    mma_tf32(c[mt][nt], a[mt], bb);
                }
        }
    }

    const int crow = blockIdx.y * 128 + m_base + g;
    const int ccol = bxx * 128 + n_base + 2 * tig;
#pragma unroll
    for (int mt = 0; mt < 4; mt++) {
#pragma unroll
        for (int nt = 0; nt < 4; nt++) {
            const int row = crow + mt * 16;
            const int col = ccol + nt * 8;
            if (FUSED && round_out) {
                uint32_t* p0 = (uint32_t*)(C + (size_t)row * N + col);
                uint32_t* p1 = (uint32_t*)(C + (size_t)(row + 8) * N + col);
                p0[0] = f2tf32(c[mt][nt][0]);
                p0[1] = f2tf32(c[mt][nt][1]);
                p1[0] = f2tf32(c[mt][nt][2]);
                p1[1] = f2tf32(c[mt][nt][3]);
            } else {
                *(float2*)(C + (size_t)row * N + col) =
                    make_float2(c[mt][nt][0], c[mt][nt][1]);
                *(float2*)(C + (size_t)(row + 8) * N + col) =
                    make_float2(c[mt][nt][2], c[mt][nt][3]);
            }
        }
    }
}

// ---------------------------------------------------------------------------
// Merged RoPE: q in-place (raw fp32); k -> g_kc[CACHE:] RNA-rounded.
// ---------------------------------------------------------------------------
__global__ void rope_qk_kernel()
{
    int idx = blockIdx.x * blockDim.x + threadIdx.x;
    int i = idx & 63;
    int h = (idx >> 6) & (NH - 1);
    int s = idx >> 11;

    float pos = (float)(s + CACHE);
    float inv_freq = exp2f(-(float)i * (13.287712379549449f / 64.f));
    float ang = pos * inv_freq;
    float sn, cs;
    sincosf(ang, &sn, &cs);

    const size_t off = ((size_t)(s * NH + h) * HD) + i;
    {
        float* p = g_q + off;
        float x1 = p[0];
        float x2 = p[64];
        p[0]  = x1 * cs - x2 * sn;
        p[64] = x2 * cs + x1 * sn;
    }
    {
        const float* p = g_k + off;
        float x1 = p[0];
        float x2 = p[64];
        uint32_t* d = (uint32_t*)(g_kc + (size_t)(CACHE + s) * DM + h * HD + i);
        d[0]  = f2tf32(x1 * cs - x2 * sn);
        d[64] = f2tf32(x2 * cs + x1 * sn);
    }
}

// ---------------------------------------------------------------------------
// Convert the KV-cache part (t < CACHE) into RNA-rounded tf32 buffers.
// ---------------------------------------------------------------------------
__global__ void convert_kv_cache_kernel(const float* __restrict__ cache_k,
                                        const float* __restrict__ cache_v)
{
    const size_t elem = ((size_t)blockIdx.x * blockDim.x + threadIdx.x) * 4;
    float4 k = *(const float4*)(cache_k + elem);
    float4 v = *(const float4*)(cache_v + elem);
    uint4 ko, vo;
    ko.x = f2tf32(k.x); ko.y = f2tf32(k.y); ko.z = f2tf32(k.z); ko.w = f2tf32(k.w);
    vo.x = f2tf32(v.x); vo.y = f2tf32(v.y); vo.z = f2tf32(v.z); vo.w = f2tf32(v.w);
    *(uint4*)(g_kc + elem) = ko;
    *(uint4*)(g_vc + elem) = vo;
}

// ---------------------------------------------------------------------------
// Tensor-core flash attention (round-11 proven core: scalar V loads,
// 512 one-job blocks, long jobs first).
// NEW: S->softmax and softmax->PV barriers are now PAIR-LOCAL named
// barriers (bar.sync 1+wr, 64): row r's score/prob data is produced and
// consumed only by warp-pair wr = r/16. Softmax rows remapped pair-locally
// (same arithmetic, bit-identical results). Only the K/V-buffer barrier
// remains CTA-wide.
// ---------------------------------------------------------------------------
#define KQSTR 132
#define VSTR  136
#define PSTR  68

#define QS_WORDS (64 * KQSTR)
#define KS_WORDS (64 * KQSTR)
#define VS_WORDS (64 * VSTR)
#define PS_WORDS (64 * PSTR)

#define FLASH_SMEM_WORDS (QS_WORDS + 2*KS_WORDS + 2*VS_WORDS + PS_WORDS + 192)
#define FLASH_SMEM_BYTES (FLASH_SMEM_WORDS * 4)

__global__ void __launch_bounds__(256, 1)
flash_tc_kernel()
{
    extern __shared__ uint32_t fsm[];
    uint32_t* Qs  = fsm;
    uint32_t* Ks0 = Qs  + QS_WORDS;
    uint32_t* Ks1 = Ks0 + KS_WORDS;
    uint32_t* Vs0 = Ks1 + KS_WORDS;
    uint32_t* Vs1 = Vs0 + VS_WORDS;
    uint32_t* Ps  = Vs1 + VS_WORDS;
    float* m_s    = (float*)(Ps + PS_WORDS);
    float* l_s    = m_s + 64;
    float* salpha = l_s + 64;
    float* PsF    = (float*)Ps;

    const int h  = blockIdx.x;
    const int qt = (S_LEN / 64 - 1) - blockIdx.y;
    const int tid = threadIdx.x;
    const int lane = tid & 31;
    const int warp = tid >> 5;
    const int g    = lane >> 2;
    const int tig  = lane & 3;
    const int wr   = warp >> 1;
    const int wc   = warp & 1;
    const int m0   = wr * 16;

    const uint32_t qs_a  = (uint32_t)__cvta_generic_to_shared(Qs);
    const uint32_t ks0_a = (uint32_t)__cvta_generic_to_shared(Ks0);
    const uint32_t ks1_a = (uint32_t)__cvta_generic_to_shared(Ks1);
    const uint32_t vs0_a = (uint32_t)__cvta_generic_to_shared(Vs0);
    const uint32_t vs1_a = (uint32_t)__cvta_generic_to_shared(Vs1);
    const uint32_t ps_a  = (uint32_t)__cvta_generic_to_shared(Ps);

    const float qscale = 0.08838834764831845f;
#pragma unroll
    for (int it = 0; it < 8; it++) {
        int idx = it * 256 + tid;
        int r = idx >> 5;
        int c = (idx & 31) << 2;
        float4 v = *(const float4*)(g_q + (size_t)(qt * 64 + r) * DM + h * HD + c);
        uint4 u;
        u.x = f2tf32(v.x * qscale);
        u.y = f2tf32(v.y * qscale);
        u.z = f2tf32(v.z * qscale);
        u.w = f2tf32(v.w * qscale);
        *(uint4*)&Qs[r * KQSTR + c] = u;
    }
    if (tid < 64) { m_s[tid] = -1e30f; l_s[tid] = 0.f; }

    auto issue_kv = [&](int kt, int b) {
        const int t0 = kt * 64;
        const uint32_t ka = b ? ks1_a : ks0_a;
        const uint32_t va = b ? vs1_a : vs0_a;
#pragma unroll
        for (int it = 0; it < 8; it++) {
            int idx = it * 256 + tid;
            int r = idx >> 5;
            int c = (idx & 31) << 2;
            size_t off = (size_t)(t0 + r) * DM + h * HD + c;
            cp16(ka + (r * KQSTR + c) * 4, g_kc + off);
            cp16(va + (r * VSTR  + c) * 4, g_vc + off);
        }
        CP_COMMIT();
    };

    issue_kv(0, 0);

    float oacc[8][4];
#pragma unroll
    for (int nt = 0; nt < 8; nt++)
#pragma unroll
        for (int i = 0; i < 4; i++) oacc[nt][i] = 0.f;

    const int arow  = m0 + (lane & 15);
    const int acolh = (lane >> 2) & 4;
    const int brow  = wc * 32 + (lane & 7) + ((lane >> 1) & 8);
    const int bcolh = (lane >> 1) & 4;

    // Pair-local softmax mapping: pair wr owns rows m0..m0+15.
    const int lt    = tid & 63;          // index within warp-pair
    const int srow  = m0 + (lt >> 2);    // softmax row (pair-local)
    const int sqd   = lt & 3;            // quad within row
    const int barid = 1 + wr;

    const int ntiles = 33 + qt;
    int p = 0;
    for (int kt = 0; kt < ntiles; kt++) {
        CP_WAIT0();
        __syncthreads();
        if (kt + 1 < ntiles) issue_kv(kt + 1, p ^ 1);

        const uint32_t ka = p ? ks1_a : ks0_a;
        const uint32_t* Vc = p ? Vs1 : Vs0;

        // ---- S = Q K^T (warp tile 16x32), ldmatrix fragments ----
        float sacc[4][4];
#pragma unroll
        for (int nt = 0; nt < 4; nt++)
#pragma unroll
            for (int i = 0; i < 4; i++) sacc[nt][i] = 0.f;

#pragma unroll
        for (int ks = 0; ks < 16; ks++) {
            const int k0 = ks * 8;
            uint32_t a[4], b[2][4];
            ldsm4(a, qs_a + (uint32_t)(arow * KQSTR + k0 + acolh) * 4);
            ldsm4(b[0], ka + (uint32_t)(brow * KQSTR + k0 + bcolh) * 4);
            ldsm4(b[1], ka + (uint32_t)((brow + 16) * KQSTR + k0 + bcolh) * 4);
#pragma unroll
            for (int nt = 0; nt < 4; nt++) {
                uint32_t bb[2] = { b[nt >> 1][(nt & 1) * 2],
                                   b[nt >> 1][(nt & 1) * 2 + 1] };
                mma_tf32(sacc[nt], a, bb);
            }
        }

        const bool diag = (kt == ntiles - 1);
        const int r0 = m0 + g, r1 = m0 + g + 8;
#pragma unroll
        for (int nt = 0; nt < 4; nt++) {
            int col = wc * 32 + nt * 8 + 2 * tig;
            float v0 = sacc[nt][0], v1 = sacc[nt][1];
            float v2 = sacc[nt][2], v3 = sacc[nt][3];
            if (diag) {
                if (col     > r0) v0 = -1e30f;
                if (col + 1 > r0) v1 = -1e30f;
                if (col     > r1) v2 = -1e30f;
                if (col + 1 > r1) v3 = -1e30f;
            }
            *(float2*)&PsF[r0 * PSTR + col] = make_float2(v0, v1);
            *(float2*)&PsF[r1 * PSTR + col] = make_float2(v2, v3);
        }
        BAR_PAIR(barid);   // pair-local: rows m0..m0+15 complete

        // ---- online softmax: pair wr handles its own 16 rows ----
        {
            float* pr = PsF + srow * PSTR + sqd * 16;
            float4 x0 = *(float4*)(pr + 0);
            float4 x1 = *(float4*)(pr + 4);
            float4 x2 = *(float4*)(pr + 8);
            float4 x3 = *(float4*)(pr + 12);
            float mp = fmaxf(fmaxf(fmaxf(x0.x, x0.y), fmaxf(x0.z, x0.w)),
                             fmaxf(fmaxf(x1.x, x1.y), fmaxf(x1.z, x1.w)));
            mp = fmaxf(mp, fmaxf(fmaxf(fmaxf(x2.x, x2.y), fmaxf(x2.z, x2.w)),
                                 fmaxf(fmaxf(x3.x, x3.y), fmaxf(x3.z, x3.w))));
            mp = fmaxf(mp, __shfl_xor_sync(0xffffffffu, mp, 1));
            mp = fmaxf(mp, __shfl_xor_sync(0xffffffffu, mp, 2));
            const float mold = m_s[srow];
            const float mx = fmaxf(mold, mp);
            float sum;
            {
                uint4 u;
                float s = 0.f;
                float p0, p1, p2, p3;
                p0 = __expf(x0.x - mx); p1 = __expf(x0.y - mx);
                p2 = __expf(x0.z - mx); p3 = __expf(x0.w - mx);
                s += (p0 + p1) + (p2 + p3);
                u.x = f2tf32(p0); u.y = f2tf32(p1); u.z = f2tf32(p2); u.w = f2tf32(p3);
                *(uint4*)(pr + 0) = u;
                p0 = __expf(x1.x - mx); p1 = __expf(x1.y - mx);
                p2 = __expf(x1.z - mx); p3 = __expf(x1.w - mx);
                s += (p0 + p1) + (p2 + p3);
                u.x = f2tf32(p0); u.y = f2tf32(p1); u.z = f2tf32(p2); u.w = f2tf32(p3);
                *(uint4*)(pr + 4) = u;
                p0 = __expf(x2.x - mx); p1 = __expf(x2.y - mx);
                p2 = __expf(x2.z - mx); p3 = __expf(x2.w - mx);
                s += (p0 + p1) + (p2 + p3);
                u.x = f2tf32(p0); u.y = f2tf32(p1); u.z = f2tf32(p2); u.w = f2tf32(p3);
                *(uint4*)(pr + 8) = u;
                p0 = __expf(x3.x - mx); p1 = __expf(x3.y - mx);
                p2 = __expf(x3.z - mx); p3 = __expf(x3.w - mx);
                s += (p0 + p1) + (p2 + p3);
                u.x = f2tf32(p0); u.y = f2tf32(p1); u.z = f2tf32(p2); u.w = f2tf32(p3);
                *(uint4*)(pr + 12) = u;
                sum = s;
            }
            sum += __shfl_xor_sync(0xffffffffu, sum, 1);
            sum += __shfl_xor_sync(0xffffffffu, sum, 2);
            __syncwarp();
            if (sqd == 0) {
                float alpha = __expf(mold - mx);
                l_s[srow] = l_s[srow] * alpha + sum;
                m_s[srow] = mx;
                salpha[srow] = alpha;
            }
        }
        BAR_PAIR(barid);   // pair-local: probs + alpha for rows m0..m0+15 ready

        // ---- rescale O, then O += P V (warp tile 16x64) ----
        {
            const float alo = salpha[m0 + g];
            const float ahi = salpha[m0 + g + 8];
#pragma unroll
            for (int nt = 0; nt < 8; nt++) {
                oacc[nt][0] *= alo; oacc[nt][1] *= alo;
                oacc[nt][2] *= ahi; oacc[nt][3] *= ahi;
            }
#pragma unroll
            for (int ks = 0; ks < 8; ks++) {
                const int k0 = ks * 8;
                uint32_t a[4];
                ldsm4(a, ps_a + (uint32_t)(arow * PSTR + k0 + acolh) * 4);
                const uint32_t* V0 = Vc + (k0 + tig) * VSTR + wc * 64 + g;
                const uint32_t* V1 = V0 + 4 * VSTR;
#pragma unroll
                for (int nt = 0; nt < 8; nt++) {
                    uint32_t b[2];
                    b[0] = V0[nt * 8];
                    b[1] = V1[nt * 8];
                    mma_tf32(oacc[nt], a, b);
                }
            }
        }
        p ^= 1;
    }

    __syncthreads();
    const float ilo = 1.f / l_s[m0 + g];
    const float ihi = 1.f / l_s[m0 + g + 8];
    const int grow = qt * 64 + m0 + g;
#pragma unroll
    for (int nt = 0; nt < 8; nt++) {
        const int col = h * HD + wc * 64 + nt * 8 + 2 * tig;
        uint32_t* d0 = (uint32_t*)(g_at + (size_t)grow * DM + col);
        uint32_t* d1 = (uint32_t*)(g_at + (size_t)(grow + 8) * DM + col);
        d0[0] = f2tf32(oacc[nt][0] * ilo);
        d0[1] = f2tf32(oacc[nt][1] * ilo);
        d1[0] = f2tf32(oacc[nt][2] * ihi);
        d1[1] = f2tf32(oacc[nt][3] * ihi);
    }
}

// ---------------------------------------------------------------------------
// Launch
// ---------------------------------------------------------------------------
extern "C" void kernel_launch(void* const* d_in, const int* in_sizes, int n_in,
                              void* d_out, int out_size)
{
    (void)in_sizes; (void)n_in; (void)out_size;
    const float* xs      = (const float*)d_in[0];
    const float* cache_k = (const float*)d_in[1];
    const float* cache_v = (const float*)d_in[2];
    const float* norm_w  = (const float*)d_in[3];
    const float* wq      = (const float*)d_in[4];
    const float* wk      = (const float*)d_in[5];
    const float* wv      = (const float*)d_in[6];
    const float* wo      = (const float*)d_in[7];
    float* out = (float*)d_out;

    float *p_xn, *p_q, *p_at, *p_vc;
    cudaGetSymbolAddress((void**)&p_xn, g_xn);
    cudaGetSymbolAddress((void**)&p_q,  g_q);
    cudaGetSymbolAddress((void**)&p_at, g_at);
    cudaGetSymbolAddress((void**)&p_vc, g_vc);

    cudaFuncSetAttribute((const void*)&sgemm_tc<true>,
                         cudaFuncAttributeMaxDynamicSharedMemorySize,
                         GEMM_SMEM_BYTES);
    cudaFuncSetAttribute((const void*)&sgemm_tc<false>,
                         cudaFuncAttributeMaxDynamicSharedMemorySize,
                         GEMM_SMEM_BYTES);
    cudaFuncSetAttribute((const void*)&flash_tc_kernel,
                         cudaFuncAttributeMaxDynamicSharedMemorySize,
                         FLASH_SMEM_BYTES);

    // 1) RMSNorm (emits tf32-rounded xn)
    rmsnorm_kernel<<<S_LEN, 256>>>(xs, norm_w);

    // 2) KV-cache conversion
    {
        const size_t n4 = (size_t)CACHE * DM / 4;
        convert_kv_cache_kernel<<<(unsigned)(n4 / 256), 256>>>(cache_k, cache_v);
    }

    // 3) Fused QKV projection (raw weights, B rounded in-register):
    //    q -> g_q, k -> g_k, v -> g_vc[CACHE:] (rounded).
    {
        dim3 gq(3 * DM / 128, S_LEN / 128);   // (96, 8)
        sgemm_tc<true><<<gq, 256, GEMM_SMEM_BYTES>>>(
            p_xn, wq, wk, wv, p_q, p_vc + (size_t)CACHE * DM, DM, DM);
    }

    // 4) Merged RoPE: q in-place; k -> rounded into g_kc[CACHE:]
    rope_qk_kernel<<<(S_LEN * NH * 64) / 256, 256>>>();

    // 5) Tensor-core flash attention (pair-local softmax barriers)
    flash_tc_kernel<<<dim3(NH, S_LEN / 64), 256, FLASH_SMEM_BYTES>>>();

    // 6) Output projection -> d_out (raw wo, B rounded in-register)
    {
        dim3 gg(DM / 128, S_LEN / 128);
        sgemm_tc<false><<<gg, 256, GEMM_SMEM_BYTES>>>(
            p_at, wo, nullptr, nullptr, out, nullptr, DM, DM);
    }
}

// round 14
// speedup vs baseline: 1.0361x; 1.0142x over previous
#include <cuda_runtime.h>
#include <math.h>
#include <stdint.h>

// Problem constants (fixed shapes for this problem instance)
#define S_LEN  1024
#define DM     4096
#define NH     32
#define HD     128
#define CACHE  2048
#define TTOT   (CACHE + S_LEN)   // 3072 total kv positions

// Scratch (device globals: allocation-free rule)
__device__ float g_xn[S_LEN * DM];
__device__ float g_q [S_LEN * DM];
__device__ float g_k [S_LEN * DM];
__device__ float g_at[S_LEN * DM];
__device__ float g_kc[(size_t)TTOT * DM];   // tf32-rounded unified K [T,H,HD]
__device__ float g_vc[(size_t)TTOT * DM];   // tf32-rounded unified V [T,H,HD]

// ---------------------------------------------------------------------------
// Common tensor-core helpers
// ---------------------------------------------------------------------------
__device__ __forceinline__ uint32_t f2tf32(float x) {
    uint32_t r;
    asm("cvt.rna.tf32.f32 %0, %1;" : "=r"(r) : "f"(x));
    return r;
}
__device__ __forceinline__ uint32_t u2tf32(uint32_t x) {
    uint32_t r;
    asm("cvt.rna.tf32.f32 %0, %1;" : "=r"(r) : "r"(x));
    return r;
}

__device__ __forceinline__ void mma_tf32(float c[4], const uint32_t a[4], const uint32_t b[2]) {
    asm volatile(
        "mma.sync.aligned.m16n8k8.row.col.f32.tf32.tf32.f32 "
        "{%0,%1,%2,%3}, {%4,%5,%6,%7}, {%8,%9}, {%0,%1,%2,%3};"
        : "+f"(c[0]), "+f"(c[1]), "+f"(c[2]), "+f"(c[3])
        : "r"(a[0]), "r"(a[1]), "r"(a[2]), "r"(a[3]), "r"(b[0]), "r"(b[1]));
}

__device__ __forceinline__ void ldsm4(uint32_t r[4], uint32_t addr) {
    asm volatile("ldmatrix.sync.aligned.m8n8.x4.shared.b16 {%0,%1,%2,%3}, [%4];"
        : "=r"(r[0]), "=r"(r[1]), "=r"(r[2]), "=r"(r[3]) : "r"(addr));
}

__device__ __forceinline__ void cp16(uint32_t dst, const void* src) {
    asm volatile("cp.async.cg.shared.global [%0], [%1], 16;" :: "r"(dst), "l"(src));
}
#define CP_COMMIT()  asm volatile("cp.async.commit_group;")
#define CP_WAIT0()   asm volatile("cp.async.wait_group 0;")
#define CP_WAIT1()   asm volatile("cp.async.wait_group 1;")

#define BAR_PAIR(id) asm volatile("bar.sync %0, 64;" :: "r"(id) : "memory")

// ---------------------------------------------------------------------------
// RMSNorm: one block per row (4096 elems), 256 threads. Emits rna tf32.
// ---------------------------------------------------------------------------
__global__ void rmsnorm_kernel(const float* __restrict__ xs,
                               const float* __restrict__ w)
{
    const int row = blockIdx.x;
    const int tid = threadIdx.x;
    const float* x = xs + (size_t)row * DM;
    float* y = g_xn + (size_t)row * DM;

    float ss = 0.f;
#pragma unroll
    for (int i = 0; i < 4; i++) {
        float4 v = *(const float4*)(x + (i * 256 + tid) * 4);
        ss += v.x * v.x + v.y * v.y + v.z * v.z + v.w * v.w;
    }
#pragma unroll
    for (int off = 16; off; off >>= 1)
        ss += __shfl_xor_sync(0xffffffffu, ss, off);

    __shared__ float red[8];
    __shared__ float s_inv;
    if ((tid & 31) == 0) red[tid >> 5] = ss;
    __syncthreads();
    if (tid == 0) {
        float t = 0.f;
#pragma unroll
        for (int i = 0; i < 8; i++) t += red[i];
        s_inv = rsqrtf(t / (float)DM + 1e-6f);
    }
    __syncthreads();
    const float inv = s_inv;
#pragma unroll
    for (int i = 0; i < 4; i++) {
        int base = (i * 256 + tid) * 4;
        float4 v = *(const float4*)(x + base);
        float4 g = *(const float4*)(w + base);
        uint4 u;
        u.x = f2tf32(v.x * inv * g.x);
        u.y = f2tf32(v.y * inv * g.y);
        u.z = f2tf32(v.z * inv * g.z);
        u.w = f2tf32(v.w * inv * g.w);
        *(uint4*)(y + base) = u;
    }
}

// ---------------------------------------------------------------------------
// TF32 tensor-core GEMM (NT): tile 128x128x32, 3-stage cp.async, ldmatrix
// fragments, stride 36. B raw fp32, rounded in registers. A pre-rounded.
// FUSED: grid.x covers q|k|v thirds; V third RNA-rounded on store -> CV.
// ---------------------------------------------------------------------------
#define GSTR 36
#define ATW  (128 * GSTR)
#define STW  (2 * ATW)
#define NST  3
#define GEMM_SMEM_BYTES (NST * STW * 4)   // 110592 B

template <bool FUSED>
__global__ void __launch_bounds__(256, 2)
sgemm_tc(const float* __restrict__ A,
         const float* __restrict__ B0, const float* __restrict__ B1,
         const float* __restrict__ B2,
         float* __restrict__ C0, float* __restrict__ CV, int N, int K)
{
    extern __shared__ uint32_t gsm[];
    const uint32_t sbase = (uint32_t)__cvta_generic_to_shared(gsm);

    const int tid  = threadIdx.x;
    const int lane = tid & 31;
    const int warp = tid >> 5;
    const int g    = lane >> 2;
    const int tig  = lane & 3;
    const int m_base = (warp >> 2) * 64;
    const int n_base = (warp & 3) * 32;

    const float* B = B0;
    float* C = C0;
    int bxx = blockIdx.x;
    bool round_out = false;
    if (FUSED) {
        const int third = blockIdx.x >> 5;       // 0:q 1:k 2:v
        bxx = blockIdx.x & 31;
        if (third == 1)      { B = B1; C = g_k; }
        else if (third == 2) { B = B2; C = CV; round_out = true; }
    }

    const int r0 = tid >> 3;
    const int c0 = (tid & 7) << 2;
    const float* Ag = A + (size_t)(blockIdx.y * 128 + r0) * K + c0;
    const float* Bg = B + (size_t)(bxx * 128 + r0) * K + c0;
    const uint32_t d0 = (uint32_t)(r0 * GSTR + c0) * 4;
    const size_t gstep = (size_t)32 * K;
    const uint32_t sstep = (uint32_t)(32 * GSTR) * 4;

    auto issue = [&](int kt) {
        const uint32_t st = sbase + (uint32_t)(kt % NST) * (STW * 4);
        const int ko = kt << 5;
        const float* a = Ag + ko;
        const float* b = Bg + ko;
#pragma unroll
        for (int it = 0; it < 4; it++) {
            cp16(st + d0 + it * sstep, a + it * gstep);
            cp16(st + ATW * 4 + d0 + it * sstep, b + it * gstep);
        }
        CP_COMMIT();
    };

    float c[4][4][4];
#pragma unroll
    for (int mt = 0; mt < 4; mt++)
#pragma unroll
        for (int nt = 0; nt < 4; nt++)
#pragma unroll
            for (int i = 0; i < 4; i++) c[mt][nt][i] = 0.f;

    issue(0); issue(1);

    const int arow  = m_base + (lane & 15);
    const int acolh = (lane >> 2) & 4;
    const int brow  = n_base + (lane & 7) + ((lane >> 1) & 8);
    const int bcolh = (lane >> 1) & 4;

    const int KT = K >> 5;
    for (int kt = 0; kt < KT; kt++) {
        if (kt + 1 < KT) { CP_WAIT1(); } else { CP_WAIT0(); }
        __syncthreads();
        if (kt + 2 < KT) issue(kt + 2);

        const uint32_t tA = sbase + (uint32_t)(kt % NST) * (STW * 4);
        const uint32_t tB = tA + ATW * 4;
#pragma unroll
        for (int kk = 0; kk < 4; kk++) {
            uint32_t a[4][4], b[2][4];
#pragma unroll
            for (int mt = 0; mt < 4; mt++)
                ldsm4(a[mt], tA + (uint32_t)((arow + mt * 16) * GSTR + kk * 8 + acolh) * 4);
            ldsm4(b[0], tB + (uint32_t)(brow * GSTR + kk * 8 + bcolh) * 4);
            ldsm4(b[1], tB + (uint32_t)((brow + 16) * GSTR + kk * 8 + bcolh) * 4);
#pragma unroll
            for (int i = 0; i < 4; i++) {
                b[0][i] = u2tf32(b[0][i]);
                b[1][i] = u2tf32(b[1][i]);
            }
#pragma unroll
            for (int mt = 0; mt < 4; mt++)
#pragma unroll
                for (int nt = 0; nt < 4; nt++) {
                    uint32_t bb[2] = { b[nt >> 1][(nt & 1) * 2],
                                       b[nt >> 1][(nt & 1) * 2 + 1] };
                    mma_tf32(c[mt][nt], a[mt], bb);
                }
        }
    }

    const int crow = blockIdx.y * 128 + m_base + g;
    const int ccol = bxx * 128 + n_base + 2 * tig;
#pragma unroll
    for (int mt = 0; mt < 4; mt++) {
#pragma unroll
        for (int nt = 0; nt < 4; nt++) {
            const int row = crow + mt * 16;
            const int col = ccol + nt * 8;
            if (FUSED && round_out) {
                uint32_t* p0 = (uint32_t*)(C + (size_t)row * N + col);
                uint32_t* p1 = (uint32_t*)(C + (size_t)(row + 8) * N + col);
                p0[0] = f2tf32(c[mt][nt][0]);
                p0[1] = f2tf32(c[mt][nt][1]);
                p1[0] = f2tf32(c[mt][nt][2]);
                p1[1] = f2tf32(c[mt][nt][3]);
            } else {
                *(float2*)(C + (size_t)row * N + col) =
                    make_float2(c[mt][nt][0], c[mt][nt][1]);
                *(float2*)(C + (size_t)(row + 8) * N + col) =
                    make_float2(c[mt][nt][2], c[mt][nt][3]);
            }
        }
    }
}

// ---------------------------------------------------------------------------
// Merged RoPE: q in-place (raw fp32); k -> g_kc[CACHE:] RNA-rounded.
// ---------------------------------------------------------------------------
__global__ void rope_qk_kernel()
{
    int idx = blockIdx.x * blockDim.x + threadIdx.x;
    int i = idx & 63;
    int h = (idx >> 6) & (NH - 1);
    int s = idx >> 11;

    float pos = (float)(s + CACHE);
    float inv_freq = exp2f(-(float)i * (13.287712379549449f / 64.f));
    float ang = pos * inv_freq;
    float sn, cs;
    sincosf(ang, &sn, &cs);

    const size_t off = ((size_t)(s * NH + h) * HD) + i;
    {
        float* p = g_q + off;
        float x1 = p[0];
        float x2 = p[64];
        p[0]  = x1 * cs - x2 * sn;
        p[64] = x2 * cs + x1 * sn;
    }
    {
        const float* p = g_k + off;
        float x1 = p[0];
        float x2 = p[64];
        uint32_t* d = (uint32_t*)(g_kc + (size_t)(CACHE + s) * DM + h * HD + i);
        d[0]  = f2tf32(x1 * cs - x2 * sn);
        d[64] = f2tf32(x2 * cs + x1 * sn);
    }
}

// ---------------------------------------------------------------------------
// Convert the KV-cache part (t < CACHE) into RNA-rounded tf32 buffers.
// ---------------------------------------------------------------------------
__global__ void convert_kv_cache_kernel(const float* __restrict__ cache_k,
                                        const float* __restrict__ cache_v)
{
    const size_t elem = ((size_t)blockIdx.x * blockDim.x + threadIdx.x) * 4;
    float4 k = *(const float4*)(cache_k + elem);
    float4 v = *(const float4*)(cache_v + elem);
    uint4 ko, vo;
    ko.x = f2tf32(k.x); ko.y = f2tf32(k.y); ko.z = f2tf32(k.z); ko.w = f2tf32(k.w);
    vo.x = f2tf32(v.x); vo.y = f2tf32(v.y); vo.z = f2tf32(v.z); vo.w = f2tf32(v.w);
    *(uint4*)(g_kc + elem) = ko;
    *(uint4*)(g_vc + elem) = vo;
}

// ---------------------------------------------------------------------------
// Tensor-core flash attention, 32-key tiles -> ~110KB smem -> 2 CTAs/SM
// so co-resident CTAs overlap their QK/softmax/PV phases.
// Pair-local softmax barriers (proven R13). 512 one-job blocks, long first.
// ---------------------------------------------------------------------------
#define KQSTR 132
#define VSTR  136
#define PSTR  36
#define TKEY  32           // keys per tile

#define QS_WORDS (64 * KQSTR)
#define KS_WORDS (TKEY * KQSTR)
#define VS_WORDS (TKEY * VSTR)
#define PS_WORDS (64 * PSTR)

#define FLASH_SMEM_WORDS (QS_WORDS + 2*KS_WORDS + 2*VS_WORDS + PS_WORDS + 192)
#define FLASH_SMEM_BYTES (FLASH_SMEM_WORDS * 4)   // ~112.4 KB

__global__ void __launch_bounds__(256, 2)
flash_tc_kernel()
{
    extern __shared__ uint32_t fsm[];
    uint32_t* Qs  = fsm;
    uint32_t* Ks0 = Qs  + QS_WORDS;
    uint32_t* Ks1 = Ks0 + KS_WORDS;
    uint32_t* Vs0 = Ks1 + KS_WORDS;
    uint32_t* Vs1 = Vs0 + VS_WORDS;
    uint32_t* Ps  = Vs1 + VS_WORDS;
    float* m_s    = (float*)(Ps + PS_WORDS);
    float* l_s    = m_s + 64;
    float* salpha = l_s + 64;
    float* PsF    = (float*)Ps;

    const int h  = blockIdx.x;
    const int qt = (S_LEN / 64 - 1) - blockIdx.y;
    const int tid = threadIdx.x;
    const int lane = tid & 31;
    const int warp = tid >> 5;
    const int g    = lane >> 2;
    const int tig  = lane & 3;
    const int wr   = warp >> 1;
    const int wc   = warp & 1;
    const int m0   = wr * 16;

    const uint32_t qs_a  = (uint32_t)__cvta_generic_to_shared(Qs);
    const uint32_t ks0_a = (uint32_t)__cvta_generic_to_shared(Ks0);
    const uint32_t ks1_a = (uint32_t)__cvta_generic_to_shared(Ks1);
    const uint32_t vs0_a = (uint32_t)__cvta_generic_to_shared(Vs0);
    const uint32_t vs1_a = (uint32_t)__cvta_generic_to_shared(Vs1);
    const uint32_t ps_a  = (uint32_t)__cvta_generic_to_shared(Ps);

    const float qscale = 0.08838834764831845f;
#pragma unroll
    for (int it = 0; it < 8; it++) {
        int idx = it * 256 + tid;
        int r = idx >> 5;
        int c = (idx & 31) << 2;
        float4 v = *(const float4*)(g_q + (size_t)(qt * 64 + r) * DM + h * HD + c);
        uint4 u;
        u.x = f2tf32(v.x * qscale);
        u.y = f2tf32(v.y * qscale);
        u.z = f2tf32(v.z * qscale);
        u.w = f2tf32(v.w * qscale);
        *(uint4*)&Qs[r * KQSTR + c] = u;
    }
    if (tid < 64) { m_s[tid] = -1e30f; l_s[tid] = 0.f; }

    // K/V tile: 32 rows x 128 floats each = 1024 chunks; 4 iters x 256 thr.
    auto issue_kv = [&](int kt, int b) {
        const int t0 = kt * TKEY;
        const uint32_t ka = b ? ks1_a : ks0_a;
        const uint32_t va = b ? vs1_a : vs0_a;
#pragma unroll
        for (int it = 0; it < 4; it++) {
            int idx = it * 256 + tid;
            int r = idx >> 5;
            int c = (idx & 31) << 2;
            size_t off = (size_t)(t0 + r) * DM + h * HD + c;
            cp16(ka + (r * KQSTR + c) * 4, g_kc + off);
            cp16(va + (r * VSTR  + c) * 4, g_vc + off);
        }
        CP_COMMIT();
    };

    issue_kv(0, 0);

    float oacc[8][4];
#pragma unroll
    for (int nt = 0; nt < 8; nt++)
#pragma unroll
        for (int i = 0; i < 4; i++) oacc[nt][i] = 0.f;

    const int arow  = m0 + (lane & 15);
    const int acolh = (lane >> 2) & 4;
    const int brow  = wc * 16 + (lane & 7) + ((lane >> 1) & 8);   // 0..31
    const int bcolh = (lane >> 1) & 4;

    // Pair-local softmax mapping: pair wr owns rows m0..m0+15;
    // 4 threads per row, 8 cols each.
    const int lt    = tid & 63;
    const int srow  = m0 + (lt >> 2);
    const int sqd   = lt & 3;
    const int barid = 1 + wr;

    const int ntiles = 66 + 2 * qt;        // (CACHE + (qt+1)*64) / 32
    const int maskb0 = -(CACHE + qt * 64); // t0 + col + maskb0 = rel col
    int p = 0;
    for (int kt = 0; kt < ntiles; kt++) {
        CP_WAIT0();
        __syncthreads();
        if (kt + 1 < ntiles) issue_kv(kt + 1, p ^ 1);

        const uint32_t ka = p ? ks1_a : ks0_a;
        const uint32_t* Vc = p ? Vs1 : Vs0;

        // ---- S = Q K^T (warp tile 16x16) ----
        float sacc[2][4];
#pragma unroll
        for (int nt = 0; nt < 2; nt++)
#pragma unroll
            for (int i = 0; i < 4; i++) sacc[nt][i] = 0.f;

#pragma unroll
        for (int ks = 0; ks < 16; ks++) {
            const int k0 = ks * 8;
            uint32_t a[4], b[4];
            ldsm4(a, qs_a + (uint32_t)(arow * KQSTR + k0 + acolh) * 4);
            ldsm4(b, ka + (uint32_t)(brow * KQSTR + k0 + bcolh) * 4);
            {
                uint32_t bb0[2] = { b[0], b[1] };
                uint32_t bb1[2] = { b[2], b[3] };
                mma_tf32(sacc[0], a, bb0);
                mma_tf32(sacc[1], a, bb1);
            }
        }

        const bool domask = (kt >= ntiles - 2);
        const int r0 = m0 + g, r1 = m0 + g + 8;
        const int mrel = kt * TKEY + maskb0;   // + col -> relative col
#pragma unroll
        for (int nt = 0; nt < 2; nt++) {
            int col = wc * 16 + nt * 8 + 2 * tig;
            float v0 = sacc[nt][0], v1 = sacc[nt][1];
            float v2 = sacc[nt][2], v3 = sacc[nt][3];
            if (domask) {
                int c0r = mrel + col, c1r = mrel + col + 1;
                if (c0r > r0) v0 = -1e30f;
                if (c1r > r0) v1 = -1e30f;
                if (c0r > r1) v2 = -1e30f;
                if (c1r > r1) v3 = -1e30f;
            }
            *(float2*)&PsF[r0 * PSTR + col] = make_float2(v0, v1);
            *(float2*)&PsF[r1 * PSTR + col] = make_float2(v2, v3);
        }
        BAR_PAIR(barid);

        // ---- online softmax: 4 threads/row, 8 cols each ----
        {
            float* pr = PsF + srow * PSTR + sqd * 8;
            float4 x0 = *(float4*)(pr + 0);
            float4 x1 = *(float4*)(pr + 4);
            float mp = fmaxf(fmaxf(fmaxf(x0.x, x0.y), fmaxf(x0.z, x0.w)),
                             fmaxf(fmaxf(x1.x, x1.y), fmaxf(x1.z, x1.w)));
            mp = fmaxf(mp, __shfl_xor_sync(0xffffffffu, mp, 1));
            mp = fmaxf(mp, __shfl_xor_sync(0xffffffffu, mp, 2));
            const float mold = m_s[srow];
            const float mx = fmaxf(mold, mp);
            float sum;
            {
                uint4 u;
                float s = 0.f;
                float p0, p1, p2, p3;
                p0 = __expf(x0.x - mx); p1 = __expf(x0.y - mx);
                p2 = __expf(x0.z - mx); p3 = __expf(x0.w - mx);
                s += (p0 + p1) + (p2 + p3);
                u.x = f2tf32(p0); u.y = f2tf32(p1); u.z = f2tf32(p2); u.w = f2tf32(p3);
                *(uint4*)(pr + 0) = u;
                p0 = __expf(x1.x - mx); p1 = __expf(x1.y - mx);
                p2 = __expf(x1.z - mx); p3 = __expf(x1.w - mx);
                s += (p0 + p1) + (p2 + p3);
                u.x = f2tf32(p0); u.y = f2tf32(p1); u.z = f2tf32(p2); u.w = f2tf32(p3);
                *(uint4*)(pr + 4) = u;
                sum = s;
            }
            sum += __shfl_xor_sync(0xffffffffu, sum, 1);
            sum += __shfl_xor_sync(0xffffffffu, sum, 2);
            __syncwarp();
            if (sqd == 0) {
                float alpha = __expf(mold - mx);
                l_s[srow] = l_s[srow] * alpha + sum;
                m_s[srow] = mx;
                salpha[srow] = alpha;
            }
        }
        BAR_PAIR(barid);

        // ---- rescale O, then O += P V (warp tile 16x64, k=32) ----
        {
            const float alo = salpha[m0 + g];
            const float ahi = salpha[m0 + g + 8];
#pragma unroll
            for (int nt = 0; nt < 8; nt++) {
                oacc[nt][0] *= alo; oacc[nt][1] *= alo;
                oacc[nt][2] *= ahi; oacc[nt][3] *= ahi;
            }
#pragma unroll
            for (int ks = 0; ks < 4; ks++) {
                const int k0 = ks * 8;
                uint32_t a[4];
                ldsm4(a, ps_a + (uint32_t)(arow * PSTR + k0 + acolh) * 4);
                const uint32_t* V0 = Vc + (k0 + tig) * VSTR + wc * 64 + g;
                const uint32_t* V1 = V0 + 4 * VSTR;
#pragma unroll
                for (int nt = 0; nt < 8; nt++) {
                    uint32_t b[2];
                    b[0] = V0[nt * 8];
                    b[1] = V1[nt * 8];
                    mma_tf32(oacc[nt], a, b);
                }
            }
        }
        p ^= 1;
    }

    __syncthreads();
    const float ilo = 1.f / l_s[m0 + g];
    const float ihi = 1.f / l_s[m0 + g + 8];
    const int grow = qt * 64 + m0 + g;
#pragma unroll
    for (int nt = 0; nt < 8; nt++) {
        const int col = h * HD + wc * 64 + nt * 8 + 2 * tig;
        uint32_t* d0 = (uint32_t*)(g_at + (size_t)grow * DM + col);
        uint32_t* d1 = (uint32_t*)(g_at + (size_t)(grow + 8) * DM + col);
        d0[0] = f2tf32(oacc[nt][0] * ilo);
        d0[1] = f2tf32(oacc[nt][1] * ilo);
        d1[0] = f2tf32(oacc[nt][2] * ihi);
        d1[1] = f2tf32(oacc[nt][3] * ihi);
    }
}

// ---------------------------------------------------------------------------
// Launch
// ---------------------------------------------------------------------------
extern "C" void kernel_launch(void* const* d_in, const int* in_sizes, int n_in,
                              void* d_out, int out_size)
{
    (void)in_sizes; (void)n_in; (void)out_size;
    const float* xs      = (const float*)d_in[0];
    const float* cache_k = (const float*)d_in[1];
    const float* cache_v = (const float*)d_in[2];
    const float* norm_w  = (const float*)d_in[3];
    const float* wq      = (const float*)d_in[4];
    const float* wk      = (const float*)d_in[5];
    const float* wv      = (const float*)d_in[6];
    const float* wo      = (const float*)d_in[7];
    float* out = (float*)d_out;

    float *p_xn, *p_q, *p_at, *p_vc;
    cudaGetSymbolAddress((void**)&p_xn, g_xn);
    cudaGetSymbolAddress((void**)&p_q,  g_q);
    cudaGetSymbolAddress((void**)&p_at, g_at);
    cudaGetSymbolAddress((void**)&p_vc, g_vc);

    cudaFuncSetAttribute((const void*)&sgemm_tc<true>,
                         cudaFuncAttributeMaxDynamicSharedMemorySize,
                         GEMM_SMEM_BYTES);
    cudaFuncSetAttribute((const void*)&sgemm_tc<false>,
                         cudaFuncAttributeMaxDynamicSharedMemorySize,
                         GEMM_SMEM_BYTES);
    cudaFuncSetAttribute((const void*)&flash_tc_kernel,
                         cudaFuncAttributeMaxDynamicSharedMemorySize,
                         FLASH_SMEM_BYTES);

    // 1) RMSNorm (emits tf32-rounded xn)
    rmsnorm_kernel<<<S_LEN, 256>>>(xs, norm_w);

    // 2) KV-cache conversion
    {
        const size_t n4 = (size_t)CACHE * DM / 4;
        convert_kv_cache_kernel<<<(unsigned)(n4 / 256), 256>>>(cache_k, cache_v);
    }

    // 3) Fused QKV projection (raw weights, B rounded in-register):
    //    q -> g_q, k -> g_k, v -> g_vc[CACHE:] (rounded).
    {
        dim3 gq(3 * DM / 128, S_LEN / 128);   // (96, 8)
        sgemm_tc<true><<<gq, 256, GEMM_SMEM_BYTES>>>(
            p_xn, wq, wk, wv, p_q, p_vc + (size_t)CACHE * DM, DM, DM);
    }

    // 4) Merged RoPE: q in-place; k -> rounded into g_kc[CACHE:]
    rope_qk_kernel<<<(S_LEN * NH * 64) / 256, 256>>>();

    // 5) Tensor-core flash attention (32-key tiles, 2 CTAs/SM)
    flash_tc_kernel<<<dim3(NH, S_LEN / 64), 256, FLASH_SMEM_BYTES>>>();

    // 6) Output projection -> d_out (raw wo, B rounded in-register)
    {
        dim3 gg(DM / 128, S_LEN / 128);
        sgemm_tc<false><<<gg, 256, GEMM_SMEM_BYTES>>>(
            p_at, wo, nullptr, nullptr, out, nullptr, DM, DM);
    }
}

// round 15
// speedup vs baseline: 1.0454x; 1.0090x over previous
#include <cuda_runtime.h>
#include <math.h>
#include <stdint.h>

// Problem constants (fixed shapes for this problem instance)
#define S_LEN  1024
#define DM     4096
#define NH     32
#define HD     128
#define CACHE  2048
#define TTOT   (CACHE + S_LEN)   // 3072 total kv positions

// Scratch (device globals: allocation-free rule)
__device__ float g_xn[S_LEN * DM];
__device__ float g_q [S_LEN * DM];
__device__ float g_k [S_LEN * DM];
__device__ float g_at[S_LEN * DM];
__device__ float g_kc[(size_t)TTOT * DM];   // tf32-rounded unified K [T,H,HD]
__device__ float g_vc[(size_t)TTOT * DM];   // tf32-rounded unified V [T,H,HD]

// ---------------------------------------------------------------------------
// Common tensor-core helpers
// ---------------------------------------------------------------------------
__device__ __forceinline__ uint32_t f2tf32(float x) {
    uint32_t r;
    asm("cvt.rna.tf32.f32 %0, %1;" : "=r"(r) : "f"(x));
    return r;
}
__device__ __forceinline__ uint32_t u2tf32(uint32_t x) {
    uint32_t r;
    asm("cvt.rna.tf32.f32 %0, %1;" : "=r"(r) : "r"(x));
    return r;
}

__device__ __forceinline__ void mma_tf32(float c[4], const uint32_t a[4], const uint32_t b[2]) {
    asm volatile(
        "mma.sync.aligned.m16n8k8.row.col.f32.tf32.tf32.f32 "
        "{%0,%1,%2,%3}, {%4,%5,%6,%7}, {%8,%9}, {%0,%1,%2,%3};"
        : "+f"(c[0]), "+f"(c[1]), "+f"(c[2]), "+f"(c[3])
        : "r"(a[0]), "r"(a[1]), "r"(a[2]), "r"(a[3]), "r"(b[0]), "r"(b[1]));
}

__device__ __forceinline__ void ldsm4(uint32_t r[4], uint32_t addr) {
    asm volatile("ldmatrix.sync.aligned.m8n8.x4.shared.b16 {%0,%1,%2,%3}, [%4];"
        : "=r"(r[0]), "=r"(r[1]), "=r"(r[2]), "=r"(r[3]) : "r"(addr));
}

__device__ __forceinline__ void cp16(uint32_t dst, const void* src) {
    asm volatile("cp.async.cg.shared.global [%0], [%1], 16;" :: "r"(dst), "l"(src));
}
#define CP_COMMIT()  asm volatile("cp.async.commit_group;")
#define CP_WAIT0()   asm volatile("cp.async.wait_group 0;")
#define CP_WAIT1()   asm volatile("cp.async.wait_group 1;")

#define BAR_PAIR(id) asm volatile("bar.sync %0, 64;" :: "r"(id) : "memory")

// ---------------------------------------------------------------------------
// RMSNorm: one block per row (4096 elems), 256 threads. Emits rna tf32.
// ---------------------------------------------------------------------------
__global__ void rmsnorm_kernel(const float* __restrict__ xs,
                               const float* __restrict__ w)
{
    const int row = blockIdx.x;
    const int tid = threadIdx.x;
    const float* x = xs + (size_t)row * DM;
    float* y = g_xn + (size_t)row * DM;

    float ss = 0.f;
#pragma unroll
    for (int i = 0; i < 4; i++) {
        float4 v = *(const float4*)(x + (i * 256 + tid) * 4);
        ss += v.x * v.x + v.y * v.y + v.z * v.z + v.w * v.w;
    }
#pragma unroll
    for (int off = 16; off; off >>= 1)
        ss += __shfl_xor_sync(0xffffffffu, ss, off);

    __shared__ float red[8];
    __shared__ float s_inv;
    if ((tid & 31) == 0) red[tid >> 5] = ss;
    __syncthreads();
    if (tid == 0) {
        float t = 0.f;
#pragma unroll
        for (int i = 0; i < 8; i++) t += red[i];
        s_inv = rsqrtf(t / (float)DM + 1e-6f);
    }
    __syncthreads();
    const float inv = s_inv;
#pragma unroll
    for (int i = 0; i < 4; i++) {
        int base = (i * 256 + tid) * 4;
        float4 v = *(const float4*)(x + base);
        float4 g = *(const float4*)(w + base);
        uint4 u;
        u.x = f2tf32(v.x * inv * g.x);
        u.y = f2tf32(v.y * inv * g.y);
        u.z = f2tf32(v.z * inv * g.z);
        u.w = f2tf32(v.w * inv * g.w);
        *(uint4*)(y + base) = u;
    }
}

// ---------------------------------------------------------------------------
// TF32 tensor-core GEMM (NT): tile 128x128x32, 3-stage cp.async, ldmatrix
// fragments, stride 36. B raw fp32, rounded in registers. A pre-rounded.
// FUSED: grid.x covers q|k|v thirds; V third RNA-rounded on store -> CV.
// ---------------------------------------------------------------------------
#define GSTR 36
#define ATW  (128 * GSTR)
#define STW  (2 * ATW)
#define NST  3
#define GEMM_SMEM_BYTES (NST * STW * 4)   // 110592 B

template <bool FUSED>
__global__ void __launch_bounds__(256, 2)
sgemm_tc(const float* __restrict__ A,
         const float* __restrict__ B0, const float* __restrict__ B1,
         const float* __restrict__ B2,
         float* __restrict__ C0, float* __restrict__ CV, int N, int K)
{
    extern __shared__ uint32_t gsm[];
    const uint32_t sbase = (uint32_t)__cvta_generic_to_shared(gsm);

    const int tid  = threadIdx.x;
    const int lane = tid & 31;
    const int warp = tid >> 5;
    const int g    = lane >> 2;
    const int tig  = lane & 3;
    const int m_base = (warp >> 2) * 64;
    const int n_base = (warp & 3) * 32;

    const float* B = B0;
    float* C = C0;
    int bxx = blockIdx.x;
    bool round_out = false;
    if (FUSED) {
        const int third = blockIdx.x >> 5;       // 0:q 1:k 2:v
        bxx = blockIdx.x & 31;
        if (third == 1)      { B = B1; C = g_k; }
        else if (third == 2) { B = B2; C = CV; round_out = true; }
    }

    const int r0 = tid >> 3;
    const int c0 = (tid & 7) << 2;
    const float* Ag = A + (size_t)(blockIdx.y * 128 + r0) * K + c0;
    const float* Bg = B + (size_t)(bxx * 128 + r0) * K + c0;
    const uint32_t d0 = (uint32_t)(r0 * GSTR + c0) * 4;
    const size_t gstep = (size_t)32 * K;
    const uint32_t sstep = (uint32_t)(32 * GSTR) * 4;

    auto issue = [&](int kt) {
        const uint32_t st = sbase + (uint32_t)(kt % NST) * (STW * 4);
        const int ko = kt << 5;
        const float* a = Ag + ko;
        const float* b = Bg + ko;
#pragma unroll
        for (int it = 0; it < 4; it++) {
            cp16(st + d0 + it * sstep, a + it * gstep);
            cp16(st + ATW * 4 + d0 + it * sstep, b + it * gstep);
        }
        CP_COMMIT();
    };

    float c[4][4][4];
#pragma unroll
    for (int mt = 0; mt < 4; mt++)
#pragma unroll
        for (int nt = 0; nt < 4; nt++)
#pragma unroll
            for (int i = 0; i < 4; i++) c[mt][nt][i] = 0.f;

    issue(0); issue(1);

    const int arow  = m_base + (lane & 15);
    const int acolh = (lane >> 2) & 4;
    const int brow  = n_base + (lane & 7) + ((lane >> 1) & 8);
    const int bcolh = (lane >> 1) & 4;

    const int KT = K >> 5;
    for (int kt = 0; kt < KT; kt++) {
        if (kt + 1 < KT) { CP_WAIT1(); } else { CP_WAIT0(); }
        __syncthreads();
        if (kt + 2 < KT) issue(kt + 2);

        const uint32_t tA = sbase + (uint32_t)(kt % NST) * (STW * 4);
        const uint32_t tB = tA + ATW * 4;
#pragma unroll
        for (int kk = 0; kk < 4; kk++) {
            uint32_t a[4][4], b[2][4];
#pragma unroll
            for (int mt = 0; mt < 4; mt++)
                ldsm4(a[mt], tA + (uint32_t)((arow + mt * 16) * GSTR + kk * 8 + acolh) * 4);
            ldsm4(b[0], tB + (uint32_t)(brow * GSTR + kk * 8 + bcolh) * 4);
            ldsm4(b[1], tB + (uint32_t)((brow + 16) * GSTR + kk * 8 + bcolh) * 4);
#pragma unroll
            for (int i = 0; i < 4; i++) {
                b[0][i] = u2tf32(b[0][i]);
                b[1][i] = u2tf32(b[1][i]);
            }
#pragma unroll
            for (int mt = 0; mt < 4; mt++)
#pragma unroll
                for (int nt = 0; nt < 4; nt++) {
                    uint32_t bb[2] = { b[nt >> 1][(nt & 1) * 2],
                                       b[nt >> 1][(nt & 1) * 2 + 1] };
                    mma_tf32(c[mt][nt], a[mt], bb);
                }
        }
    }

    const int crow = blockIdx.y * 128 + m_base + g;
    const int ccol = bxx * 128 + n_base + 2 * tig;
#pragma unroll
    for (int mt = 0; mt < 4; mt++) {
#pragma unroll
        for (int nt = 0; nt < 4; nt++) {
            const int row = crow + mt * 16;
            const int col = ccol + nt * 8;
            if (FUSED && round_out) {
                uint32_t* p0 = (uint32_t*)(C + (size_t)row * N + col);
                uint32_t* p1 = (uint32_t*)(C + (size_t)(row + 8) * N + col);
                p0[0] = f2tf32(c[mt][nt][0]);
                p0[1] = f2tf32(c[mt][nt][1]);
                p1[0] = f2tf32(c[mt][nt][2]);
                p1[1] = f2tf32(c[mt][nt][3]);
            } else {
                *(float2*)(C + (size_t)row * N + col) =
                    make_float2(c[mt][nt][0], c[mt][nt][1]);
                *(float2*)(C + (size_t)(row + 8) * N + col) =
                    make_float2(c[mt][nt][2], c[mt][nt][3]);
            }
        }
    }
}

// ---------------------------------------------------------------------------
// Merged RoPE: q in-place (raw fp32); k -> g_kc[CACHE:] RNA-rounded.
// ---------------------------------------------------------------------------
__global__ void rope_qk_kernel()
{
    int idx = blockIdx.x * blockDim.x + threadIdx.x;
    int i = idx & 63;
    int h = (idx >> 6) & (NH - 1);
    int s = idx >> 11;

    float pos = (float)(s + CACHE);
    float inv_freq = exp2f(-(float)i * (13.287712379549449f / 64.f));
    float ang = pos * inv_freq;
    float sn, cs;
    sincosf(ang, &sn, &cs);

    const size_t off = ((size_t)(s * NH + h) * HD) + i;
    {
        float* p = g_q + off;
        float x1 = p[0];
        float x2 = p[64];
        p[0]  = x1 * cs - x2 * sn;
        p[64] = x2 * cs + x1 * sn;
    }
    {
        const float* p = g_k + off;
        float x1 = p[0];
        float x2 = p[64];
        uint32_t* d = (uint32_t*)(g_kc + (size_t)(CACHE + s) * DM + h * HD + i);
        d[0]  = f2tf32(x1 * cs - x2 * sn);
        d[64] = f2tf32(x2 * cs + x1 * sn);
    }
}

// ---------------------------------------------------------------------------
// Convert the KV-cache part (t < CACHE) into RNA-rounded tf32 buffers.
// ---------------------------------------------------------------------------
__global__ void convert_kv_cache_kernel(const float* __restrict__ cache_k,
                                        const float* __restrict__ cache_v)
{
    const size_t elem = ((size_t)blockIdx.x * blockDim.x + threadIdx.x) * 4;
    float4 k = *(const float4*)(cache_k + elem);
    float4 v = *(const float4*)(cache_v + elem);
    uint4 ko, vo;
    ko.x = f2tf32(k.x); ko.y = f2tf32(k.y); ko.z = f2tf32(k.z); ko.w = f2tf32(k.w);
    vo.x = f2tf32(v.x); vo.y = f2tf32(v.y); vo.z = f2tf32(v.z); vo.w = f2tf32(v.w);
    *(uint4*)(g_kc + elem) = ko;
    *(uint4*)(g_vc + elem) = vo;
}

// ---------------------------------------------------------------------------
// Tensor-core flash attention, 32-key tiles, 2 CTAs/SM (proven R14).
// NEW: softmax fully in registers — mask, quad-shfl partial max/sum on the
// S accumulators; only one scalar per row per warp-half goes through smem
// between the two pair-barriers; P written ONCE as tf32. alpha recomputed
// locally by every lane (no salpha array).
// ---------------------------------------------------------------------------
#define KQSTR 132
#define VSTR  136
#define PSTR  36
#define TKEY  32           // keys per tile

#define QS_WORDS (64 * KQSTR)
#define KS_WORDS (TKEY * KQSTR)
#define VS_WORDS (TKEY * VSTR)
#define PS_WORDS (64 * PSTR)

#define FLASH_SMEM_WORDS (QS_WORDS + 2*KS_WORDS + 2*VS_WORDS + PS_WORDS + 384)
#define FLASH_SMEM_BYTES (FLASH_SMEM_WORDS * 4)   // ~113.2 KB

__global__ void __launch_bounds__(256, 2)
flash_tc_kernel()
{
    extern __shared__ uint32_t fsm[];
    uint32_t* Qs  = fsm;
    uint32_t* Ks0 = Qs  + QS_WORDS;
    uint32_t* Ks1 = Ks0 + KS_WORDS;
    uint32_t* Vs0 = Ks1 + KS_WORDS;
    uint32_t* Vs1 = Vs0 + VS_WORDS;
    uint32_t* Ps  = Vs1 + VS_WORDS;
    float* m_s = (float*)(Ps + PS_WORDS);
    float* l_s = m_s + 64;
    float* hm  = l_s + 64;    // [2][64] partial row max per warp-half
    float* hs  = hm + 128;    // [2][64] partial row sum per warp-half
    uint32_t* PsU = Ps;

    const int h  = blockIdx.x;
    const int qt = (S_LEN / 64 - 1) - blockIdx.y;
    const int tid = threadIdx.x;
    const int lane = tid & 31;
    const int warp = tid >> 5;
    const int g    = lane >> 2;
    const int tig  = lane & 3;
    const int wr   = warp >> 1;
    const int wc   = warp & 1;
    const int m0   = wr * 16;

    const uint32_t qs_a  = (uint32_t)__cvta_generic_to_shared(Qs);
    const uint32_t ks0_a = (uint32_t)__cvta_generic_to_shared(Ks0);
    const uint32_t ks1_a = (uint32_t)__cvta_generic_to_shared(Ks1);
    const uint32_t vs0_a = (uint32_t)__cvta_generic_to_shared(Vs0);
    const uint32_t vs1_a = (uint32_t)__cvta_generic_to_shared(Vs1);
    const uint32_t ps_a  = (uint32_t)__cvta_generic_to_shared(Ps);

    const float qscale = 0.08838834764831845f;
#pragma unroll
    for (int it = 0; it < 8; it++) {
        int idx = it * 256 + tid;
        int r = idx >> 5;
        int c = (idx & 31) << 2;
        float4 v = *(const float4*)(g_q + (size_t)(qt * 64 + r) * DM + h * HD + c);
        uint4 u;
        u.x = f2tf32(v.x * qscale);
        u.y = f2tf32(v.y * qscale);
        u.z = f2tf32(v.z * qscale);
        u.w = f2tf32(v.w * qscale);
        *(uint4*)&Qs[r * KQSTR + c] = u;
    }
    if (tid < 64) { m_s[tid] = -1e30f; l_s[tid] = 0.f; }

    auto issue_kv = [&](int kt, int b) {
        const int t0 = kt * TKEY;
        const uint32_t ka = b ? ks1_a : ks0_a;
        const uint32_t va = b ? vs1_a : vs0_a;
#pragma unroll
        for (int it = 0; it < 4; it++) {
            int idx = it * 256 + tid;
            int r = idx >> 5;
            int c = (idx & 31) << 2;
            size_t off = (size_t)(t0 + r) * DM + h * HD + c;
            cp16(ka + (r * KQSTR + c) * 4, g_kc + off);
            cp16(va + (r * VSTR  + c) * 4, g_vc + off);
        }
        CP_COMMIT();
    };

    issue_kv(0, 0);

    float oacc[8][4];
#pragma unroll
    for (int nt = 0; nt < 8; nt++)
#pragma unroll
        for (int i = 0; i < 4; i++) oacc[nt][i] = 0.f;

    const int arow  = m0 + (lane & 15);
    const int acolh = (lane >> 2) & 4;
    const int brow  = wc * 16 + (lane & 7) + ((lane >> 1) & 8);   // 0..31
    const int bcolh = (lane >> 1) & 4;
    const int barid = 1 + wr;
    const int r0 = m0 + g, r1 = m0 + g + 8;

    const int ntiles = 66 + 2 * qt;        // (CACHE + (qt+1)*64) / 32
    const int maskb0 = -(CACHE + qt * 64); // t0 + col + maskb0 = rel col
    int p = 0;
    for (int kt = 0; kt < ntiles; kt++) {
        CP_WAIT0();
        __syncthreads();
        if (kt + 1 < ntiles) issue_kv(kt + 1, p ^ 1);

        const uint32_t ka = p ? ks1_a : ks0_a;
        const uint32_t* Vc = p ? Vs1 : Vs0;

        // ---- S = Q K^T (warp tile 16x16) ----
        float sacc[2][4];
#pragma unroll
        for (int nt = 0; nt < 2; nt++)
#pragma unroll
            for (int i = 0; i < 4; i++) sacc[nt][i] = 0.f;

#pragma unroll
        for (int ks = 0; ks < 16; ks++) {
            const int k0 = ks * 8;
            uint32_t a[4], b[4];
            ldsm4(a, qs_a + (uint32_t)(arow * KQSTR + k0 + acolh) * 4);
            ldsm4(b, ka + (uint32_t)(brow * KQSTR + k0 + bcolh) * 4);
            {
                uint32_t bb0[2] = { b[0], b[1] };
                uint32_t bb1[2] = { b[2], b[3] };
                mma_tf32(sacc[0], a, bb0);
                mma_tf32(sacc[1], a, bb1);
            }
        }

        // ---- mask + partial row max in registers ----
        const bool domask = (kt >= ntiles - 2);
        const int mrel = kt * TKEY + maskb0;
        float pm0 = -1e30f, pm1 = -1e30f;
#pragma unroll
        for (int nt = 0; nt < 2; nt++) {
            const int col = wc * 16 + nt * 8 + 2 * tig;
            if (domask) {
                const int c0r = mrel + col, c1r = mrel + col + 1;
                if (c0r > r0) sacc[nt][0] = -1e30f;
                if (c1r > r0) sacc[nt][1] = -1e30f;
                if (c0r > r1) sacc[nt][2] = -1e30f;
                if (c1r > r1) sacc[nt][3] = -1e30f;
            }
            pm0 = fmaxf(pm0, fmaxf(sacc[nt][0], sacc[nt][1]));
            pm1 = fmaxf(pm1, fmaxf(sacc[nt][2], sacc[nt][3]));
        }
        pm0 = fmaxf(pm0, __shfl_xor_sync(0xffffffffu, pm0, 1));
        pm0 = fmaxf(pm0, __shfl_xor_sync(0xffffffffu, pm0, 2));
        pm1 = fmaxf(pm1, __shfl_xor_sync(0xffffffffu, pm1, 1));
        pm1 = fmaxf(pm1, __shfl_xor_sync(0xffffffffu, pm1, 2));
        if (tig == 0) {
            hm[wc * 64 + r0] = pm0;
            hm[wc * 64 + r1] = pm1;
        }
        BAR_PAIR(barid);

        // ---- combine maxes, exp in registers, store tf32 P ----
        const float mold0 = m_s[r0], mold1 = m_s[r1];
        const float mx0 = fmaxf(fmaxf(hm[r0], hm[64 + r0]), mold0);
        const float mx1 = fmaxf(fmaxf(hm[r1], hm[64 + r1]), mold1);
        const float al0 = __expf(mold0 - mx0);
        const float al1 = __expf(mold1 - mx1);
        float ps0 = 0.f, ps1 = 0.f;
#pragma unroll
        for (int nt = 0; nt < 2; nt++) {
            const int col = wc * 16 + nt * 8 + 2 * tig;
            float e0 = __expf(sacc[nt][0] - mx0);
            float e1 = __expf(sacc[nt][1] - mx0);
            float e2 = __expf(sacc[nt][2] - mx1);
            float e3 = __expf(sacc[nt][3] - mx1);
            ps0 += e0 + e1;
            ps1 += e2 + e3;
            uint32_t* d0 = &PsU[r0 * PSTR + col];
            uint32_t* d1 = &PsU[r1 * PSTR + col];
            d0[0] = f2tf32(e0); d0[1] = f2tf32(e1);
            d1[0] = f2tf32(e2); d1[1] = f2tf32(e3);
        }
        ps0 += __shfl_xor_sync(0xffffffffu, ps0, 1);
        ps0 += __shfl_xor_sync(0xffffffffu, ps0, 2);
        ps1 += __shfl_xor_sync(0xffffffffu, ps1, 1);
        ps1 += __shfl_xor_sync(0xffffffffu, ps1, 2);
        if (tig == 0) {
            hs[wc * 64 + r0] = ps0;
            hs[wc * 64 + r1] = ps1;
        }
        BAR_PAIR(barid);
        if (wc == 0 && tig == 0) {
            l_s[r0] = l_s[r0] * al0 + hs[r0] + hs[64 + r0];
            l_s[r1] = l_s[r1] * al1 + hs[r1] + hs[64 + r1];
            m_s[r0] = mx0;
            m_s[r1] = mx1;
        }

        // ---- rescale O (local alpha), then O += P V ----
        {
#pragma unroll
            for (int nt = 0; nt < 8; nt++) {
                oacc[nt][0] *= al0; oacc[nt][1] *= al0;
                oacc[nt][2] *= al1; oacc[nt][3] *= al1;
            }
#pragma unroll
            for (int ks = 0; ks < 4; ks++) {
                const int k0 = ks * 8;
                uint32_t a[4];
                ldsm4(a, ps_a + (uint32_t)(arow * PSTR + k0 + acolh) * 4);
                const uint32_t* V0 = Vc + (k0 + tig) * VSTR + wc * 64 + g;
                const uint32_t* V1 = V0 + 4 * VSTR;
#pragma unroll
                for (int nt = 0; nt < 8; nt++) {
                    uint32_t b[2];
                    b[0] = V0[nt * 8];
                    b[1] = V1[nt * 8];
                    mma_tf32(oacc[nt], a, b);
                }
            }
        }
        p ^= 1;
    }

    __syncthreads();
    const float ilo = 1.f / l_s[m0 + g];
    const float ihi = 1.f / l_s[m0 + g + 8];
    const int grow = qt * 64 + m0 + g;
#pragma unroll
    for (int nt = 0; nt < 8; nt++) {
        const int col = h * HD + wc * 64 + nt * 8 + 2 * tig;
        uint32_t* d0 = (uint32_t*)(g_at + (size_t)grow * DM + col);
        uint32_t* d1 = (uint32_t*)(g_at + (size_t)(grow + 8) * DM + col);
        d0[0] = f2tf32(oacc[nt][0] * ilo);
        d0[1] = f2tf32(oacc[nt][1] * ilo);
        d1[0] = f2tf32(oacc[nt][2] * ihi);
        d1[1] = f2tf32(oacc[nt][3] * ihi);
    }
}

// ---------------------------------------------------------------------------
// Launch
// ---------------------------------------------------------------------------
extern "C" void kernel_launch(void* const* d_in, const int* in_sizes, int n_in,
                              void* d_out, int out_size)
{
    (void)in_sizes; (void)n_in; (void)out_size;
    const float* xs      = (const float*)d_in[0];
    const float* cache_k = (const float*)d_in[1];
    const float* cache_v = (const float*)d_in[2];
    const float* norm_w  = (const float*)d_in[3];
    const float* wq      = (const float*)d_in[4];
    const float* wk      = (const float*)d_in[5];
    const float* wv      = (const float*)d_in[6];
    const float* wo      = (const float*)d_in[7];
    float* out = (float*)d_out;

    float *p_xn, *p_q, *p_at, *p_vc;
    cudaGetSymbolAddress((void**)&p_xn, g_xn);
    cudaGetSymbolAddress((void**)&p_q,  g_q);
    cudaGetSymbolAddress((void**)&p_at, g_at);
    cudaGetSymbolAddress((void**)&p_vc, g_vc);

    cudaFuncSetAttribute((const void*)&sgemm_tc<true>,
                         cudaFuncAttributeMaxDynamicSharedMemorySize,
                         GEMM_SMEM_BYTES);
    cudaFuncSetAttribute((const void*)&sgemm_tc<false>,
                         cudaFuncAttributeMaxDynamicSharedMemorySize,
                         GEMM_SMEM_BYTES);
    cudaFuncSetAttribute((const void*)&flash_tc_kernel,
                         cudaFuncAttributeMaxDynamicSharedMemorySize,
                         FLASH_SMEM_BYTES);

    // 1) RMSNorm (emits tf32-rounded xn)
    rmsnorm_kernel<<<S_LEN, 256>>>(xs, norm_w);

    // 2) KV-cache conversion
    {
        const size_t n4 = (size_t)CACHE * DM / 4;
        convert_kv_cache_kernel<<<(unsigned)(n4 / 256), 256>>>(cache_k, cache_v);
    }

    // 3) Fused QKV projection (raw weights, B rounded in-register):
    //    q -> g_q, k -> g_k, v -> g_vc[CACHE:] (rounded).
    {
        dim3 gq(3 * DM / 128, S_LEN / 128);   // (96, 8)
        sgemm_tc<true><<<gq, 256, GEMM_SMEM_BYTES>>>(
            p_xn, wq, wk, wv, p_q, p_vc + (size_t)CACHE * DM, DM, DM);
    }

    // 4) Merged RoPE: q in-place; k -> rounded into g_kc[CACHE:]
    rope_qk_kernel<<<(S_LEN * NH * 64) / 256, 256>>>();

    // 5) Tensor-core flash attention (register softmax, 2 CTAs/SM)
    flash_tc_kernel<<<dim3(NH, S_LEN / 64), 256, FLASH_SMEM_BYTES>>>();

    // 6) Output projection -> d_out (raw wo, B rounded in-register)
    {
        dim3 gg(DM / 128, S_LEN / 128);
        sgemm_tc<false><<<gg, 256, GEMM_SMEM_BYTES>>>(
            p_at, wo, nullptr, nullptr, out, nullptr, DM, DM);
    }
}

// round 16
// speedup vs baseline: 1.0988x; 1.0511x over previous
#include <cuda_runtime.h>
#include <math.h>
#include <stdint.h>

// Problem constants (fixed shapes for this problem instance)
#define S_LEN  1024
#define DM     4096
#define NH     32
#define HD     128
#define CACHE  2048
#define TTOT   (CACHE + S_LEN)   // 3072 total kv positions

// Scratch (device globals: allocation-free rule)
__device__ float g_xn[S_LEN * DM];
__device__ float g_q [S_LEN * DM];
__device__ float g_k [S_LEN * DM];
__device__ float g_at[S_LEN * DM];
__device__ float g_kc[(size_t)TTOT * DM];   // tf32-rounded unified K [T,H,HD]
__device__ float g_vc[(size_t)TTOT * DM];   // tf32-rounded unified V [T,H,HD]

// ---------------------------------------------------------------------------
// Common tensor-core helpers
// ---------------------------------------------------------------------------
__device__ __forceinline__ uint32_t f2tf32(float x) {
    uint32_t r;
    asm("cvt.rna.tf32.f32 %0, %1;" : "=r"(r) : "f"(x));
    return r;
}
__device__ __forceinline__ uint32_t u2tf32(uint32_t x) {
    uint32_t r;
    asm("cvt.rna.tf32.f32 %0, %1;" : "=r"(r) : "r"(x));
    return r;
}

__device__ __forceinline__ void mma_tf32(float c[4], const uint32_t a[4], const uint32_t b[2]) {
    asm volatile(
        "mma.sync.aligned.m16n8k8.row.col.f32.tf32.tf32.f32 "
        "{%0,%1,%2,%3}, {%4,%5,%6,%7}, {%8,%9}, {%0,%1,%2,%3};"
        : "+f"(c[0]), "+f"(c[1]), "+f"(c[2]), "+f"(c[3])
        : "r"(a[0]), "r"(a[1]), "r"(a[2]), "r"(a[3]), "r"(b[0]), "r"(b[1]));
}

__device__ __forceinline__ void ldsm4(uint32_t r[4], uint32_t addr) {
    asm volatile("ldmatrix.sync.aligned.m8n8.x4.shared.b16 {%0,%1,%2,%3}, [%4];"
        : "=r"(r[0]), "=r"(r[1]), "=r"(r[2]), "=r"(r[3]) : "r"(addr));
}

__device__ __forceinline__ void cp16(uint32_t dst, const void* src) {
    asm volatile("cp.async.cg.shared.global [%0], [%1], 16;" :: "r"(dst), "l"(src));
}
#define CP_COMMIT()  asm volatile("cp.async.commit_group;")
#define CP_WAIT0()   asm volatile("cp.async.wait_group 0;")
#define CP_WAIT1()   asm volatile("cp.async.wait_group 1;")

#define BAR_PAIR(id) asm volatile("bar.sync %0, 64;" :: "r"(id) : "memory")

// ---------------------------------------------------------------------------
// RMSNorm: one block per row (4096 elems), 256 threads. Emits rna tf32.
// ---------------------------------------------------------------------------
__global__ void rmsnorm_kernel(const float* __restrict__ xs,
                               const float* __restrict__ w)
{
    const int row = blockIdx.x;
    const int tid = threadIdx.x;
    const float* x = xs + (size_t)row * DM;
    float* y = g_xn + (size_t)row * DM;

    float ss = 0.f;
#pragma unroll
    for (int i = 0; i < 4; i++) {
        float4 v = *(const float4*)(x + (i * 256 + tid) * 4);
        ss += v.x * v.x + v.y * v.y + v.z * v.z + v.w * v.w;
    }
#pragma unroll
    for (int off = 16; off; off >>= 1)
        ss += __shfl_xor_sync(0xffffffffu, ss, off);

    __shared__ float red[8];
    __shared__ float s_inv;
    if ((tid & 31) == 0) red[tid >> 5] = ss;
    __syncthreads();
    if (tid == 0) {
        float t = 0.f;
#pragma unroll
        for (int i = 0; i < 8; i++) t += red[i];
        s_inv = rsqrtf(t / (float)DM + 1e-6f);
    }
    __syncthreads();
    const float inv = s_inv;
#pragma unroll
    for (int i = 0; i < 4; i++) {
        int base = (i * 256 + tid) * 4;
        float4 v = *(const float4*)(x + base);
        float4 g = *(const float4*)(w + base);
        uint4 u;
        u.x = f2tf32(v.x * inv * g.x);
        u.y = f2tf32(v.y * inv * g.y);
        u.z = f2tf32(v.z * inv * g.z);
        u.w = f2tf32(v.w * inv * g.w);
        *(uint4*)(y + base) = u;
    }
}

// ---------------------------------------------------------------------------
// TF32 tensor-core GEMM (NT): tile 128x128x32, 3-stage cp.async, ldmatrix
// fragments, stride 36. B raw fp32, rounded in registers. A pre-rounded.
// FUSED: grid.x covers q|k|v thirds; V third RNA-rounded on store -> CV.
// ---------------------------------------------------------------------------
#define GSTR 36
#define ATW  (128 * GSTR)
#define STW  (2 * ATW)
#define NST  3
#define GEMM_SMEM_BYTES (NST * STW * 4)   // 110592 B

template <bool FUSED>
__global__ void __launch_bounds__(256, 2)
sgemm_tc(const float* __restrict__ A,
         const float* __restrict__ B0, const float* __restrict__ B1,
         const float* __restrict__ B2,
         float* __restrict__ C0, float* __restrict__ CV, int N, int K)
{
    extern __shared__ uint32_t gsm[];
    const uint32_t sbase = (uint32_t)__cvta_generic_to_shared(gsm);

    const int tid  = threadIdx.x;
    const int lane = tid & 31;
    const int warp = tid >> 5;
    const int g    = lane >> 2;
    const int tig  = lane & 3;
    const int m_base = (warp >> 2) * 64;
    const int n_base = (warp & 3) * 32;

    const float* B = B0;
    float* C = C0;
    int bxx = blockIdx.x;
    bool round_out = false;
    if (FUSED) {
        const int third = blockIdx.x >> 5;       // 0:q 1:k 2:v
        bxx = blockIdx.x & 31;
        if (third == 1)      { B = B1; C = g_k; }
        else if (third == 2) { B = B2; C = CV; round_out = true; }
    }

    const int r0 = tid >> 3;
    const int c0 = (tid & 7) << 2;
    const float* Ag = A + (size_t)(blockIdx.y * 128 + r0) * K + c0;
    const float* Bg = B + (size_t)(bxx * 128 + r0) * K + c0;
    const uint32_t d0 = (uint32_t)(r0 * GSTR + c0) * 4;
    const size_t gstep = (size_t)32 * K;
    const uint32_t sstep = (uint32_t)(32 * GSTR) * 4;

    auto issue = [&](int kt) {
        const uint32_t st = sbase + (uint32_t)(kt % NST) * (STW * 4);
        const int ko = kt << 5;
        const float* a = Ag + ko;
        const float* b = Bg + ko;
#pragma unroll
        for (int it = 0; it < 4; it++) {
            cp16(st + d0 + it * sstep, a + it * gstep);
            cp16(st + ATW * 4 + d0 + it * sstep, b + it * gstep);
        }
        CP_COMMIT();
    };

    float c[4][4][4];
#pragma unroll
    for (int mt = 0; mt < 4; mt++)
#pragma unroll
        for (int nt = 0; nt < 4; nt++)
#pragma unroll
            for (int i = 0; i < 4; i++) c[mt][nt][i] = 0.f;

    issue(0); issue(1);

    const int arow  = m_base + (lane & 15);
    const int acolh = (lane >> 2) & 4;
    const int brow  = n_base + (lane & 7) + ((lane >> 1) & 8);
    const int bcolh = (lane >> 1) & 4;

    const int KT = K >> 5;
    for (int kt = 0; kt < KT; kt++) {
        if (kt + 1 < KT) { CP_WAIT1(); } else { CP_WAIT0(); }
        __syncthreads();
        if (kt + 2 < KT) issue(kt + 2);

        const uint32_t tA = sbase + (uint32_t)(kt % NST) * (STW * 4);
        const uint32_t tB = tA + ATW * 4;
#pragma unroll
        for (int kk = 0; kk < 4; kk++) {
            uint32_t a[4][4], b[2][4];
#pragma unroll
            for (int mt = 0; mt < 4; mt++)
                ldsm4(a[mt], tA + (uint32_t)((arow + mt * 16) * GSTR + kk * 8 + acolh) * 4);
            ldsm4(b[0], tB + (uint32_t)(brow * GSTR + kk * 8 + bcolh) * 4);
            ldsm4(b[1], tB + (uint32_t)((brow + 16) * GSTR + kk * 8 + bcolh) * 4);
#pragma unroll
            for (int i = 0; i < 4; i++) {
                b[0][i] = u2tf32(b[0][i]);
                b[1][i] = u2tf32(b[1][i]);
            }
#pragma unroll
            for (int mt = 0; mt < 4; mt++)
#pragma unroll
                for (int nt = 0; nt < 4; nt++) {
                    uint32_t bb[2] = { b[nt >> 1][(nt & 1) * 2],
                                       b[nt >> 1][(nt & 1) * 2 + 1] };
                    mma_tf32(c[mt][nt], a[mt], bb);
                }
        }
    }

    const int crow = blockIdx.y * 128 + m_base + g;
    const int ccol = bxx * 128 + n_base + 2 * tig;
#pragma unroll
    for (int mt = 0; mt < 4; mt++) {
#pragma unroll
        for (int nt = 0; nt < 4; nt++) {
            const int row = crow + mt * 16;
            const int col = ccol + nt * 8;
            if (FUSED && round_out) {
                uint32_t* p0 = (uint32_t*)(C + (size_t)row * N + col);
                uint32_t* p1 = (uint32_t*)(C + (size_t)(row + 8) * N + col);
                p0[0] = f2tf32(c[mt][nt][0]);
                p0[1] = f2tf32(c[mt][nt][1]);
                p1[0] = f2tf32(c[mt][nt][2]);
                p1[1] = f2tf32(c[mt][nt][3]);
            } else {
                *(float2*)(C + (size_t)row * N + col) =
                    make_float2(c[mt][nt][0], c[mt][nt][1]);
                *(float2*)(C + (size_t)(row + 8) * N + col) =
                    make_float2(c[mt][nt][2], c[mt][nt][3]);
            }
        }
    }
}

// ---------------------------------------------------------------------------
// Merged RoPE: q in-place (raw fp32); k -> g_kc[CACHE:] RNA-rounded.
// ---------------------------------------------------------------------------
__global__ void rope_qk_kernel()
{
    int idx = blockIdx.x * blockDim.x + threadIdx.x;
    int i = idx & 63;
    int h = (idx >> 6) & (NH - 1);
    int s = idx >> 11;

    float pos = (float)(s + CACHE);
    float inv_freq = exp2f(-(float)i * (13.287712379549449f / 64.f));
    float ang = pos * inv_freq;
    float sn, cs;
    sincosf(ang, &sn, &cs);

    const size_t off = ((size_t)(s * NH + h) * HD) + i;
    {
        float* p = g_q + off;
        float x1 = p[0];
        float x2 = p[64];
        p[0]  = x1 * cs - x2 * sn;
        p[64] = x2 * cs + x1 * sn;
    }
    {
        const float* p = g_k + off;
        float x1 = p[0];
        float x2 = p[64];
        uint32_t* d = (uint32_t*)(g_kc + (size_t)(CACHE + s) * DM + h * HD + i);
        d[0]  = f2tf32(x1 * cs - x2 * sn);
        d[64] = f2tf32(x2 * cs + x1 * sn);
    }
}

// ---------------------------------------------------------------------------
// Convert the KV-cache part (t < CACHE) into RNA-rounded tf32 buffers.
// ---------------------------------------------------------------------------
__global__ void convert_kv_cache_kernel(const float* __restrict__ cache_k,
                                        const float* __restrict__ cache_v)
{
    const size_t elem = ((size_t)blockIdx.x * blockDim.x + threadIdx.x) * 4;
    float4 k = *(const float4*)(cache_k + elem);
    float4 v = *(const float4*)(cache_v + elem);
    uint4 ko, vo;
    ko.x = f2tf32(k.x); ko.y = f2tf32(k.y); ko.z = f2tf32(k.z); ko.w = f2tf32(k.w);
    vo.x = f2tf32(v.x); vo.y = f2tf32(v.y); vo.z = f2tf32(v.z); vo.w = f2tf32(v.w);
    *(uint4*)(g_kc + elem) = ko;
    *(uint4*)(g_vc + elem) = vo;
}

// ---------------------------------------------------------------------------
// Tensor-core flash attention, 32-key tiles, 2 CTAs/SM, register softmax
// (proven R15). NEW: Q fragments preloaded ONCE into registers (qf[16][4])
// — removes the per-tile Q ldmatrix (half the QK smem-crossbar traffic,
// which is the binding resource).
// ---------------------------------------------------------------------------
#define KQSTR 132
#define VSTR  136
#define PSTR  36
#define TKEY  32           // keys per tile

#define QS_WORDS (64 * KQSTR)
#define KS_WORDS (TKEY * KQSTR)
#define VS_WORDS (TKEY * VSTR)
#define PS_WORDS (64 * PSTR)

#define FLASH_SMEM_WORDS (QS_WORDS + 2*KS_WORDS + 2*VS_WORDS + PS_WORDS + 384)
#define FLASH_SMEM_BYTES (FLASH_SMEM_WORDS * 4)   // ~113.2 KB

__global__ void __launch_bounds__(256, 2)
flash_tc_kernel()
{
    extern __shared__ uint32_t fsm[];
    uint32_t* Qs  = fsm;
    uint32_t* Ks0 = Qs  + QS_WORDS;
    uint32_t* Ks1 = Ks0 + KS_WORDS;
    uint32_t* Vs0 = Ks1 + KS_WORDS;
    uint32_t* Vs1 = Vs0 + VS_WORDS;
    uint32_t* Ps  = Vs1 + VS_WORDS;
    float* m_s = (float*)(Ps + PS_WORDS);
    float* l_s = m_s + 64;
    float* hm  = l_s + 64;    // [2][64] partial row max per warp-half
    float* hs  = hm + 128;    // [2][64] partial row sum per warp-half
    uint32_t* PsU = Ps;

    const int h  = blockIdx.x;
    const int qt = (S_LEN / 64 - 1) - blockIdx.y;
    const int tid = threadIdx.x;
    const int lane = tid & 31;
    const int warp = tid >> 5;
    const int g    = lane >> 2;
    const int tig  = lane & 3;
    const int wr   = warp >> 1;
    const int wc   = warp & 1;
    const int m0   = wr * 16;

    const uint32_t qs_a  = (uint32_t)__cvta_generic_to_shared(Qs);
    const uint32_t ks0_a = (uint32_t)__cvta_generic_to_shared(Ks0);
    const uint32_t ks1_a = (uint32_t)__cvta_generic_to_shared(Ks1);
    const uint32_t vs0_a = (uint32_t)__cvta_generic_to_shared(Vs0);
    const uint32_t vs1_a = (uint32_t)__cvta_generic_to_shared(Vs1);
    const uint32_t ps_a  = (uint32_t)__cvta_generic_to_shared(Ps);

    const float qscale = 0.08838834764831845f;
#pragma unroll
    for (int it = 0; it < 8; it++) {
        int idx = it * 256 + tid;
        int r = idx >> 5;
        int c = (idx & 31) << 2;
        float4 v = *(const float4*)(g_q + (size_t)(qt * 64 + r) * DM + h * HD + c);
        uint4 u;
        u.x = f2tf32(v.x * qscale);
        u.y = f2tf32(v.y * qscale);
        u.z = f2tf32(v.z * qscale);
        u.w = f2tf32(v.w * qscale);
        *(uint4*)&Qs[r * KQSTR + c] = u;
    }
    if (tid < 64) { m_s[tid] = -1e30f; l_s[tid] = 0.f; }

    auto issue_kv = [&](int kt, int b) {
        const int t0 = kt * TKEY;
        const uint32_t ka = b ? ks1_a : ks0_a;
        const uint32_t va = b ? vs1_a : vs0_a;
#pragma unroll
        for (int it = 0; it < 4; it++) {
            int idx = it * 256 + tid;
            int r = idx >> 5;
            int c = (idx & 31) << 2;
            size_t off = (size_t)(t0 + r) * DM + h * HD + c;
            cp16(ka + (r * KQSTR + c) * 4, g_kc + off);
            cp16(va + (r * VSTR  + c) * 4, g_vc + off);
        }
        CP_COMMIT();
    };

    issue_kv(0, 0);

    const int arow  = m0 + (lane & 15);
    const int acolh = (lane >> 2) & 4;
    const int brow  = wc * 16 + (lane & 7) + ((lane >> 1) & 8);   // 0..31
    const int bcolh = (lane >> 1) & 4;
    const int barid = 1 + wr;
    const int r0 = m0 + g, r1 = m0 + g + 8;

    // ---- Preload ALL Q fragments into registers (once per block) ----
    __syncthreads();
    uint32_t qf[16][4];
#pragma unroll
    for (int ks = 0; ks < 16; ks++)
        ldsm4(qf[ks], qs_a + (uint32_t)(arow * KQSTR + ks * 8 + acolh) * 4);

    float oacc[8][4];
#pragma unroll
    for (int nt = 0; nt < 8; nt++)
#pragma unroll
        for (int i = 0; i < 4; i++) oacc[nt][i] = 0.f;

    const int ntiles = 66 + 2 * qt;        // (CACHE + (qt+1)*64) / 32
    const int maskb0 = -(CACHE + qt * 64); // t0 + col + maskb0 = rel col
    int p = 0;
    for (int kt = 0; kt < ntiles; kt++) {
        CP_WAIT0();
        __syncthreads();
        if (kt + 1 < ntiles) issue_kv(kt + 1, p ^ 1);

        const uint32_t ka = p ? ks1_a : ks0_a;
        const uint32_t* Vc = p ? Vs1 : Vs0;

        // ---- S = Q K^T (warp tile 16x16), Q from registers ----
        float sacc[2][4];
#pragma unroll
        for (int nt = 0; nt < 2; nt++)
#pragma unroll
            for (int i = 0; i < 4; i++) sacc[nt][i] = 0.f;

#pragma unroll
        for (int ks = 0; ks < 16; ks++) {
            const int k0 = ks * 8;
            uint32_t b[4];
            ldsm4(b, ka + (uint32_t)(brow * KQSTR + k0 + bcolh) * 4);
            {
                uint32_t bb0[2] = { b[0], b[1] };
                uint32_t bb1[2] = { b[2], b[3] };
                mma_tf32(sacc[0], qf[ks], bb0);
                mma_tf32(sacc[1], qf[ks], bb1);
            }
        }

        // ---- mask + partial row max in registers ----
        const bool domask = (kt >= ntiles - 2);
        const int mrel = kt * TKEY + maskb0;
        float pm0 = -1e30f, pm1 = -1e30f;
#pragma unroll
        for (int nt = 0; nt < 2; nt++) {
            const int col = wc * 16 + nt * 8 + 2 * tig;
            if (domask) {
                const int c0r = mrel + col, c1r = mrel + col + 1;
                if (c0r > r0) sacc[nt][0] = -1e30f;
                if (c1r > r0) sacc[nt][1] = -1e30f;
                if (c0r > r1) sacc[nt][2] = -1e30f;
                if (c1r > r1) sacc[nt][3] = -1e30f;
            }
            pm0 = fmaxf(pm0, fmaxf(sacc[nt][0], sacc[nt][1]));
            pm1 = fmaxf(pm1, fmaxf(sacc[nt][2], sacc[nt][3]));
        }
        pm0 = fmaxf(pm0, __shfl_xor_sync(0xffffffffu, pm0, 1));
        pm0 = fmaxf(pm0, __shfl_xor_sync(0xffffffffu, pm0, 2));
        pm1 = fmaxf(pm1, __shfl_xor_sync(0xffffffffu, pm1, 1));
        pm1 = fmaxf(pm1, __shfl_xor_sync(0xffffffffu, pm1, 2));
        if (tig == 0) {
            hm[wc * 64 + r0] = pm0;
            hm[wc * 64 + r1] = pm1;
        }
        BAR_PAIR(barid);

        // ---- combine maxes, exp in registers, store tf32 P ----
        const float mold0 = m_s[r0], mold1 = m_s[r1];
        const float mx0 = fmaxf(fmaxf(hm[r0], hm[64 + r0]), mold0);
        const float mx1 = fmaxf(fmaxf(hm[r1], hm[64 + r1]), mold1);
        const float al0 = __expf(mold0 - mx0);
        const float al1 = __expf(mold1 - mx1);
        float ps0 = 0.f, ps1 = 0.f;
#pragma unroll
        for (int nt = 0; nt < 2; nt++) {
            const int col = wc * 16 + nt * 8 + 2 * tig;
            float e0 = __expf(sacc[nt][0] - mx0);
            float e1 = __expf(sacc[nt][1] - mx0);
            float e2 = __expf(sacc[nt][2] - mx1);
            float e3 = __expf(sacc[nt][3] - mx1);
            ps0 += e0 + e1;
            ps1 += e2 + e3;
            uint32_t* d0 = &PsU[r0 * PSTR + col];
            uint32_t* d1 = &PsU[r1 * PSTR + col];
            d0[0] = f2tf32(e0); d0[1] = f2tf32(e1);
            d1[0] = f2tf32(e2); d1[1] = f2tf32(e3);
        }
        ps0 += __shfl_xor_sync(0xffffffffu, ps0, 1);
        ps0 += __shfl_xor_sync(0xffffffffu, ps0, 2);
        ps1 += __shfl_xor_sync(0xffffffffu, ps1, 1);
        ps1 += __shfl_xor_sync(0xffffffffu, ps1, 2);
        if (tig == 0) {
            hs[wc * 64 + r0] = ps0;
            hs[wc * 64 + r1] = ps1;
        }
        BAR_PAIR(barid);
        if (wc == 0 && tig == 0) {
            l_s[r0] = l_s[r0] * al0 + hs[r0] + hs[64 + r0];
            l_s[r1] = l_s[r1] * al1 + hs[r1] + hs[64 + r1];
            m_s[r0] = mx0;
            m_s[r1] = mx1;
        }

        // ---- rescale O (local alpha), then O += P V ----
        {
#pragma unroll
            for (int nt = 0; nt < 8; nt++) {
                oacc[nt][0] *= al0; oacc[nt][1] *= al0;
                oacc[nt][2] *= al1; oacc[nt][3] *= al1;
            }
#pragma unroll
            for (int ks = 0; ks < 4; ks++) {
                const int k0 = ks * 8;
                uint32_t a[4];
                ldsm4(a, ps_a + (uint32_t)(arow * PSTR + k0 + acolh) * 4);
                const uint32_t* V0 = Vc + (k0 + tig) * VSTR + wc * 64 + g;
                const uint32_t* V1 = V0 + 4 * VSTR;
#pragma unroll
                for (int nt = 0; nt < 8; nt++) {
                    uint32_t b[2];
                    b[0] = V0[nt * 8];
                    b[1] = V1[nt * 8];
                    mma_tf32(oacc[nt], a, b);
                }
            }
        }
        p ^= 1;
    }

    __syncthreads();
    const float ilo = 1.f / l_s[m0 + g];
    const float ihi = 1.f / l_s[m0 + g + 8];
    const int grow = qt * 64 + m0 + g;
#pragma unroll
    for (int nt = 0; nt < 8; nt++) {
        const int col = h * HD + wc * 64 + nt * 8 + 2 * tig;
        uint32_t* d0 = (uint32_t*)(g_at + (size_t)grow * DM + col);
        uint32_t* d1 = (uint32_t*)(g_at + (size_t)(grow + 8) * DM + col);
        d0[0] = f2tf32(oacc[nt][0] * ilo);
        d0[1] = f2tf32(oacc[nt][1] * ilo);
        d1[0] = f2tf32(oacc[nt][2] * ihi);
        d1[1] = f2tf32(oacc[nt][3] * ihi);
    }
}

// ---------------------------------------------------------------------------
// Launch
// ---------------------------------------------------------------------------
extern "C" void kernel_launch(void* const* d_in, const int* in_sizes, int n_in,
                              void* d_out, int out_size)
{
    (void)in_sizes; (void)n_in; (void)out_size;
    const float* xs      = (const float*)d_in[0];
    const float* cache_k = (const float*)d_in[1];
    const float* cache_v = (const float*)d_in[2];
    const float* norm_w  = (const float*)d_in[3];
    const float* wq      = (const float*)d_in[4];
    const float* wk      = (const float*)d_in[5];
    const float* wv      = (const float*)d_in[6];
    const float* wo      = (const float*)d_in[7];
    float* out = (float*)d_out;

    float *p_xn, *p_q, *p_at, *p_vc;
    cudaGetSymbolAddress((void**)&p_xn, g_xn);
    cudaGetSymbolAddress((void**)&p_q,  g_q);
    cudaGetSymbolAddress((void**)&p_at, g_at);
    cudaGetSymbolAddress((void**)&p_vc, g_vc);

    cudaFuncSetAttribute((const void*)&sgemm_tc<true>,
                         cudaFuncAttributeMaxDynamicSharedMemorySize,
                         GEMM_SMEM_BYTES);
    cudaFuncSetAttribute((const void*)&sgemm_tc<false>,
                         cudaFuncAttributeMaxDynamicSharedMemorySize,
                         GEMM_SMEM_BYTES);
    cudaFuncSetAttribute((const void*)&flash_tc_kernel,
                         cudaFuncAttributeMaxDynamicSharedMemorySize,
                         FLASH_SMEM_BYTES);

    // 1) RMSNorm (emits tf32-rounded xn)
    rmsnorm_kernel<<<S_LEN, 256>>>(xs, norm_w);

    // 2) KV-cache conversion
    {
        const size_t n4 = (size_t)CACHE * DM / 4;
        convert_kv_cache_kernel<<<(unsigned)(n4 / 256), 256>>>(cache_k, cache_v);
    }

    // 3) Fused QKV projection (raw weights, B rounded in-register):
    //    q -> g_q, k -> g_k, v -> g_vc[CACHE:] (rounded).
    {
        dim3 gq(3 * DM / 128, S_LEN / 128);   // (96, 8)
        sgemm_tc<true><<<gq, 256, GEMM_SMEM_BYTES>>>(
            p_xn, wq, wk, wv, p_q, p_vc + (size_t)CACHE * DM, DM, DM);
    }

    // 4) Merged RoPE: q in-place; k -> rounded into g_kc[CACHE:]
    rope_qk_kernel<<<(S_LEN * NH * 64) / 256, 256>>>();

    // 5) Tensor-core flash attention (register Q + register softmax)
    flash_tc_kernel<<<dim3(NH, S_LEN / 64), 256, FLASH_SMEM_BYTES>>>();

    // 6) Output projection -> d_out (raw wo, B rounded in-register)
    {
        dim3 gg(DM / 128, S_LEN / 128);
        sgemm_tc<false><<<gg, 256, GEMM_SMEM_BYTES>>>(
            p_at, wo, nullptr, nullptr, out, nullptr, DM, DM);
    }
}